// round 10
// baseline (speedup 1.0000x reference)
#include <cuda_runtime.h>
#include <cuda_bf16.h>
#include <math.h>
#include <stdint.h>

#define BATCH 16
#define CCH   512
#define NPIX  4096
#define KSPLIT 4

// ---------------- scratch (__device__ globals; no allocation allowed) ----------------
__device__ float g_Gp  [(size_t)KSPLIT * BATCH * CCH * CCH];
__device__ float g_G   [(size_t)BATCH * CCH * CCH];
__device__ float g_T1  [(size_t)BATCH * CCH * CCH];
__device__ float g_S   [(size_t)BATCH * CCH * CCH];
__device__ float g_attn[(size_t)BATCH * CCH * CCH];
__device__ float g_T2  [(size_t)BATCH * CCH * CCH];
__device__ float g_P   [(size_t)BATCH * CCH * CCH];
__device__ float g_ga  [BATCH * CCH];
__device__ float g_be  [BATCH * CCH];
__device__ float g_sx  [BATCH * CCH];
__device__ float g_hs  [BATCH * CCH];
__device__ float g_u   [BATCH * CCH];
__device__ float g_w   [BATCH * CCH];
__device__ float g_v1  [BATCH * CCH];
__device__ float g_t   [BATCH * CCH];
__device__ float g_r   [BATCH * CCH];

// ---------------- bf16 split helpers ----------------
// x = hi + lo (hi: rn-bf16, lo: rn-bf16 of remainder) -> ~16-bit effective mantissa
__device__ __forceinline__ void bsplit2(float x0, float x1, uint32_t& hi, uint32_t& lo)
{
    __nv_bfloat16 h0 = __float2bfloat16(x0), h1 = __float2bfloat16(x1);
    float f0 = __bfloat162float(h0), f1 = __bfloat162float(h1);
    __nv_bfloat16 l0 = __float2bfloat16(x0 - f0), l1 = __float2bfloat16(x1 - f1);
    __nv_bfloat162 H(h0, h1), L(l0, l1);
    hi = *reinterpret_cast<uint32_t*>(&H);
    lo = *reinterpret_cast<uint32_t*>(&L);
}

__device__ __forceinline__ void mma_bf16(float* d, const uint32_t* a, const uint32_t* b)
{
    asm volatile(
        "mma.sync.aligned.m16n8k16.row.col.f32.bf16.bf16.f32 "
        "{%0,%1,%2,%3}, {%4,%5,%6,%7}, {%8,%9}, {%0,%1,%2,%3};"
        : "+f"(d[0]), "+f"(d[1]), "+f"(d[2]), "+f"(d[3])
        : "r"(a[0]), "r"(a[1]), "r"(a[2]), "r"(a[3]), "r"(b[0]), "r"(b[1]));
}

// ---------------- GroupNorm stats: emits ga/be/sx/hs ----------------
__global__ void gn_stats_kernel(const float* __restrict__ x,
                                const float* __restrict__ gamma,
                                const float* __restrict__ beta)
{
    int bg = blockIdx.x;
    int b = bg >> 5, g = bg & 31;
    size_t base = (size_t)bg * (16 * NPIX);
    int wid = threadIdx.x >> 5, lane = threadIdx.x & 31;
    __shared__ float chs[16], chss[16];
    __shared__ float2 st_sh;

#pragma unroll
    for (int c2 = 0; c2 < 2; c2++) {
        int cl = wid * 2 + c2;
        const float4* xp = (const float4*)(x + base + (size_t)cl * NPIX);
        float s = 0.f, ss = 0.f;
        for (int i = lane; i < NPIX / 4; i += 32) {
            float4 v = xp[i];
            s  += v.x + v.y + v.z + v.w;
            ss += v.x * v.x + v.y * v.y + v.z * v.z + v.w * v.w;
        }
#pragma unroll
        for (int o = 16; o > 0; o >>= 1) {
            s  += __shfl_xor_sync(0xffffffffu, s, o);
            ss += __shfl_xor_sync(0xffffffffu, ss, o);
        }
        if (lane == 0) { chs[cl] = s; chss[cl] = ss; }
    }
    __syncthreads();
    if (threadIdx.x == 0) {
        float s = 0.f, ss = 0.f;
#pragma unroll
        for (int i = 0; i < 16; i++) { s += chs[i]; ss += chss[i]; }
        float mean = s * (1.f / (16 * NPIX));
        float var  = ss * (1.f / (16 * NPIX)) - mean * mean;
        st_sh = make_float2(mean, rsqrtf(var + 1e-6f));
    }
    __syncthreads();
    if (threadIdx.x < 16) {
        int cl = threadIdx.x, ch = g * 16 + cl;
        float2 st = st_sh;
        float ga = gamma[ch] * st.y;
        float be = beta[ch] - st.x * ga;
        float sx = chs[cl];
        int idx = (b << 9) + ch;
        g_ga[idx] = ga;
        g_be[idx] = be;
        g_sx[idx] = sx;
        g_hs[idx] = ga * sx + (float)NPIX * be;
    }
}

// ---------------- split-bf16 mma GEMM: D = scale*A*OP(B) (+bias)(+resid)(*cscale) ----------------
// CTA 256x128, BK=32, 8 warps (4x2), warp tile 64x64, m16n8k16 bf16, fp32 acc.
// 2-plane split: D ~= Ahi*Bhi + Ahi*Blo + Alo*Bhi  (error ~2^-16 per product).
// BNN=false: B read as [N,K] row-major (D = A*B^T).  BNN=true: B read as [K,N] row-major (D = A*B).
#define A_SUB 132                        // b32 stride per 16x16 A subtile (128 used)
#define B_SUB 66                         // b32 stride per 8x16 B subtile (64 used) — EVEN for LDS.64 alignment
#define A_PLANE (32 * A_SUB)             // 4224 b32 (16 mt x 2 kt)
#define B_PLANE (32 * B_SUB)             // 2112 b32 (16 nt x 2 kt)
#define OFF_BHI (2 * A_PLANE)            // 8448
#define OFF_BLO (2 * A_PLANE + B_PLANE)  // 10560
#define STAGE_U32 (2 * A_PLANE + 2 * B_PLANE)   // 12672
#define SMEM_SZ (2 * STAGE_U32 * 4)             // 101376 B

template<bool BNN>
__global__ void __launch_bounds__(256, 1) gemm_tc(
    const float* __restrict__ A, int lda, long long sA,
    const float* __restrict__ B, int ldb, long long sB,
    float* __restrict__ D, int ldd, long long sD,
    const float* __restrict__ bias, int bias_mode, long long sBias,
    const float* __restrict__ resid,
    const float* __restrict__ cscale,
    float scale, int K, int sym, long long sKsp)
{
    extern __shared__ uint32_t smem_u[];

    int tid = threadIdx.x, wid = tid >> 5, lane = tid & 31;
    int z = blockIdx.z;
    int row0, col0;
    if (sym) {
        int t = blockIdx.x;
        row0 = (t < 2) ? 0 : 256;
        col0 = ((t < 2) ? t : (t - 2)) << 7;
    } else {
        row0 = blockIdx.y << 8;
        col0 = blockIdx.x << 7;
    }

    A += (size_t)z * sA + (size_t)row0 * lda;
    B += (size_t)z * sB;
    D += (size_t)z * sD;
    if (sym) {
        A += (size_t)blockIdx.y * K;
        B += (size_t)blockIdx.y * K;     // sym is NT-only
        D += (size_t)blockIdx.y * sKsp;
    }
    if (resid) resid += (size_t)z * sD;

    // ---- staging thread mapping ----
    const int r_  = tid >> 3;            // 0..31 (base row, +32 per i)
    const int c0_ = (tid & 7) << 2;      // k within stage: 0..28 step 4
    const int kt_  = c0_ >> 4;           // 16-k subtile
    const int kp_  = (c0_ & 15) >> 1;    // b32 pair index within kt: 0,2,4,6
    const int khi_ = kp_ >> 2, kpm_ = kp_ & 3;

    int offA[8], offB[4];
#pragma unroll
    for (int i = 0; i < 8; i++) {
        int r = r_ + (i << 5);           // 0..255
        int mt = r >> 4, rr = r & 15, gr = rr & 7, hf = rr >> 3;
        offA[i] = (mt * 2 + kt_) * A_SUB + (gr * 4 + kpm_) * 4 + hf + (khi_ << 1);
    }
    if (!BNN) {
#pragma unroll
        for (int i = 0; i < 4; i++) {
            int n = r_ + (i << 5);       // 0..127
            int nt = n >> 3, nn = n & 7;
            offB[i] = (nt * 2 + kt_) * B_SUB + (nn * 4 + kpm_) * 2 + khi_;
        }
    }

    const float* aG = A + (size_t)r_ * lda + c0_;
    const size_t aStep = (size_t)32 * lda;
    const float* bG;
    size_t bIstep, bSstep;
    if (BNN) {
        bG = B + col0 + (size_t)(tid >> 5) * ldb + ((size_t)(tid & 31) << 2);
        bIstep = (size_t)8 * ldb;
        bSstep = (size_t)32 * ldb;
    } else {
        bG = B + (size_t)(col0 + r_) * ldb + c0_;
        bIstep = (size_t)32 * ldb;
        bSstep = 32;
    }

    const int wm4 = (wid & 3) * 4;       // 4 mt (16-row) groups
    const int wn8 = (wid >> 2) * 8;      // 8 nt (8-col) groups

    float acc[4][8][4];
#pragma unroll
    for (int mt = 0; mt < 4; mt++)
#pragma unroll
        for (int nt = 0; nt < 8; nt++)
#pragma unroll
            for (int rgi = 0; rgi < 4; rgi++) acc[mt][nt][rgi] = 0.f;

    const int NK = K >> 5;
    float4 ra[8], rb[4];

    auto stage_load = [&](int s) {
        const float* aN = aG + (size_t)s * 32;
#pragma unroll
        for (int i = 0; i < 8; i++) ra[i] = *(const float4*)(aN + i * aStep);
        const float* bN = bG + (size_t)s * bSstep;
#pragma unroll
        for (int i = 0; i < 4; i++) rb[i] = *(const float4*)(bN + i * bIstep);
    };

    auto stage_store = [&](uint32_t* sb) {
#pragma unroll
        for (int i = 0; i < 8; i++) {
            uint32_t h01, l01, h23, l23;
            bsplit2(ra[i].x, ra[i].y, h01, l01);
            bsplit2(ra[i].z, ra[i].w, h23, l23);
            sb[offA[i]]               = h01;
            sb[offA[i] + 4]           = h23;     // second k-pair: kpm+1 -> +4 words
            sb[A_PLANE + offA[i]]     = l01;
            sb[A_PLANE + offA[i] + 4] = l23;
        }
        if (!BNN) {
#pragma unroll
            for (int i = 0; i < 4; i++) {
                uint32_t h01, l01, h23, l23;
                bsplit2(rb[i].x, rb[i].y, h01, l01);
                bsplit2(rb[i].z, rb[i].w, h23, l23);
                sb[OFF_BHI + offB[i]]     = h01;
                sb[OFF_BHI + offB[i] + 2] = h23;   // kpm+1 -> +2 words
                sb[OFF_BLO + offB[i]]     = l01;
                sb[OFF_BLO + offB[i] + 2] = l23;
            }
        } else {
            // B from [K,N]: all lanes of a warp share k; scatter bf16 halves
            int k0 = tid >> 5;
            int n0 = (tid & 31) << 2;
#pragma unroll
            for (int i = 0; i < 4; i++) {
                int k = k0 + (i << 3);
                int kt = k >> 4, kl = k & 15, kp = kl >> 1;
                int khi = kp >> 2, kpm = kp & 3, kb = k & 1;
                float vals[4] = { rb[i].x, rb[i].y, rb[i].z, rb[i].w };
#pragma unroll
                for (int m = 0; m < 4; m++) {
                    int n = n0 + m, nt = n >> 3, nn = n & 7;
                    int idx = (nt * 2 + kt) * B_SUB + (nn * 4 + kpm) * 2 + khi;
                    __nv_bfloat16 h = __float2bfloat16(vals[m]);
                    __nv_bfloat16 l = __float2bfloat16(vals[m] - __bfloat162float(h));
                    ((__nv_bfloat16*)(sb + OFF_BHI))[idx * 2 + kb] = h;
                    ((__nv_bfloat16*)(sb + OFF_BLO))[idx * 2 + kb] = l;
                }
            }
        }
    };

    stage_load(0);
    stage_store(smem_u);
    __syncthreads();

    for (int s = 0; s < NK; s++) {
        if (s + 1 < NK) stage_load(s + 1);
        const uint32_t* cS = smem_u + (s & 1) * STAGE_U32;
#pragma unroll
        for (int kt = 0; kt < 2; kt++) {
            uint4 af[4]; uint2 bf[8];
#pragma unroll
            for (int mt = 0; mt < 4; mt++)
                af[mt] = *(const uint4*)(cS + ((wm4 + mt) * 2 + kt) * A_SUB + (lane << 2));
#pragma unroll
            for (int nt = 0; nt < 8; nt++)
                bf[nt] = *(const uint2*)(cS + OFF_BHI + ((wn8 + nt) * 2 + kt) * B_SUB + (lane << 1));
            // hi * hi
#pragma unroll
            for (int mt = 0; mt < 4; mt++)
#pragma unroll
                for (int nt = 0; nt < 8; nt++)
                    mma_bf16(acc[mt][nt], &af[mt].x, &bf[nt].x);
            // lo * hi
            {
                uint4 al[4];
#pragma unroll
                for (int mt = 0; mt < 4; mt++)
                    al[mt] = *(const uint4*)(cS + A_PLANE + ((wm4 + mt) * 2 + kt) * A_SUB + (lane << 2));
#pragma unroll
                for (int mt = 0; mt < 4; mt++)
#pragma unroll
                    for (int nt = 0; nt < 8; nt++)
                        mma_bf16(acc[mt][nt], &al[mt].x, &bf[nt].x);
            }
            // hi * lo
            {
                uint2 bl[8];
#pragma unroll
                for (int nt = 0; nt < 8; nt++)
                    bl[nt] = *(const uint2*)(cS + OFF_BLO + ((wn8 + nt) * 2 + kt) * B_SUB + (lane << 1));
#pragma unroll
                for (int mt = 0; mt < 4; mt++)
#pragma unroll
                    for (int nt = 0; nt < 8; nt++)
                        mma_bf16(acc[mt][nt], &af[mt].x, &bl[nt].x);
            }
        }
        if (s + 1 < NK) {
            stage_store(smem_u + ((s + 1) & 1) * STAGE_U32);
            __syncthreads();
        }
    }

    // ---- epilogue (C fragment layout identical to m16n8k8) ----
    const int lane4 = lane >> 2, laneq = lane & 3;
    const int wrow = row0 + (wid & 3) * 64;
    const int wcol = col0 + (wid >> 2) * 64;
#pragma unroll
    for (int mt = 0; mt < 4; mt++) {
#pragma unroll
        for (int half = 0; half < 2; half++) {
            int r = wrow + mt * 16 + lane4 + half * 8;
            float rb_ = (bias_mode == 1) ? bias[(size_t)z * sBias + r] : 0.f;
            float* drow = D + (size_t)r * ldd + wcol;
            const float* rrow = resid ? (resid + (size_t)r * ldd + wcol) : nullptr;
#pragma unroll
            for (int nt = 0; nt < 8; nt++) {
                int c = nt * 8 + laneq * 2;
                float2 o;
                o.x = acc[mt][nt][half * 2 + 0] * scale;
                o.y = acc[mt][nt][half * 2 + 1] * scale;
                if (cscale) {
                    o.x *= cscale[(size_t)z * CCH + wcol + c];
                    o.y *= cscale[(size_t)z * CCH + wcol + c + 1];
                }
                o.x += rb_; o.y += rb_;
                if (bias_mode == 2) {
                    o.x += bias[(size_t)z * sBias + wcol + c];
                    o.y += bias[(size_t)z * sBias + wcol + c + 1];
                }
                if (rrow) { o.x += rrow[c]; o.y += rrow[c + 1]; }
                *(float2*)(drow + c) = o;
            }
        }
    }
}

// ---------------- reduce split-K Gram partials + exact GN rank-1 corrections ----------------
__global__ void __launch_bounds__(256) reduce_g_kernel(const float* __restrict__ Gp,
                                                       float* __restrict__ G)
{
    const size_t per = (size_t)BATCH * CCH * CCH;
    int b = blockIdx.y;
    int idx = (blockIdx.x * 256 + threadIdx.x) << 2;
    int i = idx >> 9, j = idx & 511;
    if (i < 256 && j >= 256) return;
    size_t off = (size_t)b * CCH * CCH + idx;
    float4 s0 = *(const float4*)(Gp + off);
    float4 s1 = *(const float4*)(Gp + per + off);
    float4 s2 = *(const float4*)(Gp + 2 * per + off);
    float4 s3 = *(const float4*)(Gp + 3 * per + off);
    int ri = (b << 9) + i, rj = (b << 9) + j;
    float gai = g_ga[ri], hsxi = gai * g_sx[ri], bei = g_be[ri];
    float4 gaj = *(const float4*)(g_ga + rj);
    float4 bej = *(const float4*)(g_be + rj);
    float4 hsj = *(const float4*)(g_hs + rj);
    float4 o;
    o.x = gai * gaj.x * ((s0.x + s1.x) + (s2.x + s3.x)) + hsxi * bej.x + bei * hsj.x;
    o.y = gai * gaj.y * ((s0.y + s1.y) + (s2.y + s3.y)) + hsxi * bej.y + bei * hsj.y;
    o.z = gai * gaj.z * ((s0.z + s1.z) + (s2.z + s3.z)) + hsxi * bej.z + bei * hsj.z;
    o.w = gai * gaj.w * ((s0.w + s1.w) + (s2.w + s3.w)) + hsxi * bej.w + bei * hsj.w;
    *(float4*)(G + off) = o;
}

// ---------------- mirror upper-right block of symmetric G ----------------
__global__ void __launch_bounds__(256) mirror_kernel(float* __restrict__ G)
{
    __shared__ float t[32][33];
    float* Gb = G + (size_t)blockIdx.z * CCH * CCH;
    int i0 = blockIdx.y << 5, j0 = 256 + (blockIdx.x << 5);
    int lx = threadIdx.x & 31, ly = threadIdx.x >> 5;
#pragma unroll
    for (int ii = 0; ii < 4; ii++)
        t[ly + ii * 8][lx] = Gb[(size_t)(j0 + ly + ii * 8) * CCH + i0 + lx];
    __syncthreads();
#pragma unroll
    for (int ii = 0; ii < 4; ii++)
        Gb[(size_t)(i0 + ly + ii * 8) * CCH + j0 + lx] = t[lx][ly + ii * 8];
}

// ---------------- softmax with rank-1 bias corrections ----------------
__global__ void softmax_kernel(const float* __restrict__ S, float* __restrict__ attn,
                               const float* __restrict__ u, const float* __restrict__ w,
                               const float* __restrict__ bq, const float* __restrict__ bk,
                               float scale)
{
    int gw = (blockIdx.x * blockDim.x + threadIdx.x) >> 5;
    int lane = threadIdx.x & 31;
    if (gw >= BATCH * CCH) return;
    int b = gw >> 9, c = gw & 511;
    const float* row = S + (size_t)gw * CCH;
    float* orow = attn + (size_t)gw * CCH;
    float uc = u[(b << 9) + c], bqc = bq[c];
    float v[16];
    float m = -3.4e38f;
#pragma unroll
    for (int i = 0; i < 16; i++) {
        int d = lane + (i << 5);
        float bkd = bk[d], wd = w[(b << 9) + d];
        v[i] = scale * (row[d] + uc * bkd + bqc * wd + (float)NPIX * bqc * bkd);
        m = fmaxf(m, v[i]);
    }
#pragma unroll
    for (int o = 16; o > 0; o >>= 1) m = fmaxf(m, __shfl_xor_sync(0xffffffffu, m, o));
    float s = 0.f;
#pragma unroll
    for (int i = 0; i < 16; i++) { v[i] = __expf(v[i] - m); s += v[i]; }
#pragma unroll
    for (int o = 16; o > 0; o >>= 1) s += __shfl_xor_sync(0xffffffffu, s, o);
    float inv = 1.f / s;
#pragma unroll
    for (int i = 0; i < 16; i++) orow[lane + (i << 5)] = v[i] * inv;
}

// ---------------- batched matvec: y[b,m] = W_b[m,:].(v_b + v2) (+bias[m]) ----------------
__global__ void matvec_kernel(const float* __restrict__ W, long long sW,
                              const float* __restrict__ v, long long sV,
                              const float* __restrict__ v2,
                              float* __restrict__ y, long long sY,
                              const float* __restrict__ bias)
{
    int b = blockIdx.y;
    int m = (blockIdx.x << 3) + (threadIdx.x >> 5);
    int lane = threadIdx.x & 31;
    const float* wr = W + (size_t)b * sW + (size_t)m * CCH;
    const float* vv = v + (size_t)b * sV;
    float s = 0.f;
    for (int k = lane; k < CCH; k += 32) {
        float vk = vv[k];
        if (v2) vk += v2[k];
        s += wr[k] * vk;
    }
#pragma unroll
    for (int o = 16; o > 0; o >>= 1) s += __shfl_xor_sync(0xffffffffu, s, o);
    if (lane == 0) y[(size_t)b * sY + m] = s + (bias ? bias[m] : 0.f);
}

__global__ void matvec_uw_kernel(const float* __restrict__ Wq, const float* __restrict__ Wk,
                                 const float* __restrict__ hs,
                                 float* __restrict__ u, float* __restrict__ w)
{
    const float* W = blockIdx.z ? Wk : Wq;
    float* y = blockIdx.z ? w : u;
    int b = blockIdx.y;
    int m = (blockIdx.x << 3) + (threadIdx.x >> 5);
    int lane = threadIdx.x & 31;
    const float* wr = W + (size_t)m * CCH;
    const float* vv = hs + (size_t)b * CCH;
    float s = 0.f;
    for (int k = lane; k < CCH; k += 32) s += wr[k] * vv[k];
#pragma unroll
    for (int o = 16; o > 0; o >>= 1) s += __shfl_xor_sync(0xffffffffu, s, o);
    if (lane == 0) y[(size_t)b * CCH + m] = s;
}

// ---------------- launch ----------------
extern "C" void kernel_launch(void* const* d_in, const int* in_sizes, int n_in,
                              void* d_out, int out_size)
{
    const float* x     = (const float*)d_in[0];
    const float* gamma = (const float*)d_in[1];
    const float* beta  = (const float*)d_in[2];
    const float* Wq    = (const float*)d_in[3];
    const float* bq    = (const float*)d_in[4];
    const float* Wk    = (const float*)d_in[5];
    const float* bk    = (const float*)d_in[6];
    const float* Wv    = (const float*)d_in[7];
    const float* bv    = (const float*)d_in[8];
    const float* Wo    = (const float*)d_in[9];
    const float* bo    = (const float*)d_in[10];
    float* out = (float*)d_out;

    float *Gp, *G, *T1, *S, *attn, *T2, *P;
    float *ga, *be, *hs, *u, *w, *v1, *t, *r;
    cudaGetSymbolAddress((void**)&Gp,    g_Gp);
    cudaGetSymbolAddress((void**)&G,     g_G);
    cudaGetSymbolAddress((void**)&T1,    g_T1);
    cudaGetSymbolAddress((void**)&S,     g_S);
    cudaGetSymbolAddress((void**)&attn,  g_attn);
    cudaGetSymbolAddress((void**)&T2,    g_T2);
    cudaGetSymbolAddress((void**)&P,     g_P);
    cudaGetSymbolAddress((void**)&ga,    g_ga);
    cudaGetSymbolAddress((void**)&be,    g_be);
    cudaGetSymbolAddress((void**)&hs,    g_hs);
    cudaGetSymbolAddress((void**)&u,     g_u);
    cudaGetSymbolAddress((void**)&w,     g_w);
    cudaGetSymbolAddress((void**)&v1,    g_v1);
    cudaGetSymbolAddress((void**)&t,     g_t);
    cudaGetSymbolAddress((void**)&r,     g_r);

    cudaFuncSetAttribute((const void*)gemm_tc<false>, cudaFuncAttributeMaxDynamicSharedMemorySize, SMEM_SZ);
    cudaFuncSetAttribute((const void*)gemm_tc<true>,  cudaFuncAttributeMaxDynamicSharedMemorySize, SMEM_SZ);

    const long long sF  = (long long)CCH * NPIX;
    const long long sAt = (long long)CCH * CCH;
    const long long sKsp = (long long)BATCH * CCH * CCH;
    const float scale = 1.0f / sqrtf((float)CCH);

    // 1) stats (ga/be/sx/hs), bias-correction vectors
    gn_stats_kernel<<<BATCH * 32, 256>>>(x, gamma, beta);
    matvec_uw_kernel<<<dim3(CCH / 8, BATCH, 2), 256>>>(Wq, Wk, hs, u, w);

    // 2) Gx = x x^T (raw Gram, NT sym), split-K; reduce + GN corrections; mirror
    gemm_tc<false><<<dim3(6, KSPLIT, BATCH), 256, SMEM_SZ>>>(
        x, NPIX, sF, x, NPIX, sF, Gp, CCH, sAt,
        nullptr, 0, 0, nullptr, nullptr, 1.f, NPIX / KSPLIT, 1, sKsp);
    reduce_g_kernel<<<dim3(256, BATCH), 256>>>(Gp, G);
    mirror_kernel<<<dim3(8, 8, BATCH), 256>>>(G);

    // 3) T1 = Wq G (NT, G symmetric); S = T1 Wk^T (NT)
    gemm_tc<false><<<dim3(4, 2, BATCH), 256, SMEM_SZ>>>(
        Wq, CCH, 0, G, CCH, sAt, T1, CCH, sAt, nullptr, 0, 0, nullptr, nullptr, 1.f, CCH, 0, 0);
    gemm_tc<false><<<dim3(4, 2, BATCH), 256, SMEM_SZ>>>(
        T1, CCH, sAt, Wk, CCH, 0, S, CCH, sAt, nullptr, 0, 0, nullptr, nullptr, 1.f, CCH, 0, 0);

    // 4) softmax (rank-1 bias corrections)
    softmax_kernel<<<(BATCH * CCH * 32) / 256, 256>>>(S, attn, u, w, bq, bk, scale);

    // 5) T2 = Wo attn (BNN); P' = (T2 Wv) (BNN) * diag(ga)
    gemm_tc<true><<<dim3(4, 2, BATCH), 256, SMEM_SZ>>>(
        Wo, CCH, 0, attn, CCH, sAt, T2, CCH, sAt, nullptr, 0, 0, nullptr, nullptr, 1.f, CCH, 0, 0);
    gemm_tc<true><<<dim3(4, 2, BATCH), 256, SMEM_SZ>>>(
        T2, CCH, sAt, Wv, CCH, 0, P, CCH, sAt, nullptr, 0, 0, nullptr, ga, 1.f, CCH, 0, 0);

    // 6) r = Wo (attn (Wv be + bv)) + bo
    matvec_kernel<<<dim3(CCH / 8, BATCH), 256>>>(Wv, 0, be, CCH, nullptr, v1, CCH, nullptr);
    matvec_kernel<<<dim3(CCH / 8, BATCH), 256>>>(attn, sAt, v1, CCH, bv, t, CCH, nullptr);
    matvec_kernel<<<dim3(CCH / 8, BATCH), 256>>>(Wo, 0, t, CCH, nullptr, r, CCH, bo);

    // 7) out = P' x + r + x   (BNN: B = x [K=512, N=4096] directly)
    gemm_tc<true><<<dim3(NPIX / 128, 2, BATCH), 256, SMEM_SZ>>>(
        P, CCH, sAt, x, NPIX, sF, out, NPIX, sF, r, 1, CCH, x, nullptr, 1.f, CCH, 0, 0);
}

// round 11
// speedup vs baseline: 1.0845x; 1.0845x over previous
#include <cuda_runtime.h>
#include <cuda_bf16.h>
#include <math.h>
#include <stdint.h>

#define BATCH 16
#define CCH   512
#define NPIX  4096
#define KSPLIT 4

// ---------------- scratch (__device__ globals; no allocation allowed) ----------------
__device__ float g_xT  [(size_t)BATCH * NPIX * CCH];   // raw x transposed [b, p, c]
__device__ float g_Gp  [(size_t)KSPLIT * BATCH * CCH * CCH];
__device__ float g_G   [(size_t)BATCH * CCH * CCH];
__device__ float g_T1  [(size_t)BATCH * CCH * CCH];
__device__ float g_S   [(size_t)BATCH * CCH * CCH];
__device__ float g_attn[(size_t)BATCH * CCH * CCH];
__device__ float g_attnT[(size_t)BATCH * CCH * CCH];
__device__ float g_T2  [(size_t)BATCH * CCH * CCH];
__device__ float g_P   [(size_t)BATCH * CCH * CCH];
__device__ float g_WvT [(size_t)CCH * CCH];
__device__ float g_ga  [BATCH * CCH];
__device__ float g_be  [BATCH * CCH];
__device__ float g_sx  [BATCH * CCH];
__device__ float g_hs  [BATCH * CCH];
__device__ float g_u   [BATCH * CCH];
__device__ float g_w   [BATCH * CCH];
__device__ float g_v1  [BATCH * CCH];
__device__ float g_t   [BATCH * CCH];
__device__ float g_r   [BATCH * CCH];

// ---------------- helpers ----------------
__device__ __forceinline__ float tf32r(float x) {
    float y; asm("cvt.rna.tf32.f32 %0, %1;" : "=f"(y) : "f"(x)); return y;
}
__device__ __forceinline__ void bsplit2(float x0, float x1, uint32_t& hi, uint32_t& lo)
{
    __nv_bfloat16 h0 = __float2bfloat16(x0), h1 = __float2bfloat16(x1);
    float f0 = __bfloat162float(h0), f1 = __bfloat162float(h1);
    __nv_bfloat16 l0 = __float2bfloat16(x0 - f0), l1 = __float2bfloat16(x1 - f1);
    __nv_bfloat162 H(h0, h1), L(l0, l1);
    hi = *reinterpret_cast<uint32_t*>(&H);
    lo = *reinterpret_cast<uint32_t*>(&L);
}
__device__ __forceinline__ void mma_tf32(float* d, const uint32_t* a, const uint32_t* b) {
    asm volatile(
        "mma.sync.aligned.m16n8k8.row.col.f32.tf32.tf32.f32 "
        "{%0,%1,%2,%3}, {%4,%5,%6,%7}, {%8,%9}, {%0,%1,%2,%3};"
        : "+f"(d[0]), "+f"(d[1]), "+f"(d[2]), "+f"(d[3])
        : "r"(a[0]), "r"(a[1]), "r"(a[2]), "r"(a[3]), "r"(b[0]), "r"(b[1]));
}
__device__ __forceinline__ void mma_bf16(float* d, const uint32_t* a, const uint32_t* b) {
    asm volatile(
        "mma.sync.aligned.m16n8k16.row.col.f32.bf16.bf16.f32 "
        "{%0,%1,%2,%3}, {%4,%5,%6,%7}, {%8,%9}, {%0,%1,%2,%3};"
        : "+f"(d[0]), "+f"(d[1]), "+f"(d[2]), "+f"(d[3])
        : "r"(a[0]), "r"(a[1]), "r"(a[2]), "r"(a[3]), "r"(b[0]), "r"(b[1]));
}

// ---------------- GroupNorm stats: emits ga/be/sx/hs ----------------
__global__ void gn_stats_kernel(const float* __restrict__ x,
                                const float* __restrict__ gamma,
                                const float* __restrict__ beta)
{
    int bg = blockIdx.x;
    int b = bg >> 5, g = bg & 31;
    size_t base = (size_t)bg * (16 * NPIX);
    int wid = threadIdx.x >> 5, lane = threadIdx.x & 31;
    __shared__ float chs[16], chss[16];
    __shared__ float2 st_sh;

#pragma unroll
    for (int c2 = 0; c2 < 2; c2++) {
        int cl = wid * 2 + c2;
        const float4* xp = (const float4*)(x + base + (size_t)cl * NPIX);
        float s = 0.f, ss = 0.f;
        for (int i = lane; i < NPIX / 4; i += 32) {
            float4 v = xp[i];
            s  += v.x + v.y + v.z + v.w;
            ss += v.x * v.x + v.y * v.y + v.z * v.z + v.w * v.w;
        }
#pragma unroll
        for (int o = 16; o > 0; o >>= 1) {
            s  += __shfl_xor_sync(0xffffffffu, s, o);
            ss += __shfl_xor_sync(0xffffffffu, ss, o);
        }
        if (lane == 0) { chs[cl] = s; chss[cl] = ss; }
    }
    __syncthreads();
    if (threadIdx.x == 0) {
        float s = 0.f, ss = 0.f;
#pragma unroll
        for (int i = 0; i < 16; i++) { s += chs[i]; ss += chss[i]; }
        float mean = s * (1.f / (16 * NPIX));
        float var  = ss * (1.f / (16 * NPIX)) - mean * mean;
        st_sh = make_float2(mean, rsqrtf(var + 1e-6f));
    }
    __syncthreads();
    if (threadIdx.x < 16) {
        int cl = threadIdx.x, ch = g * 16 + cl;
        float2 st = st_sh;
        float ga = gamma[ch] * st.y;
        float be = beta[ch] - st.x * ga;
        float sx = chs[cl];
        int idx = (b << 9) + ch;
        g_ga[idx] = ga;
        g_be[idx] = be;
        g_sx[idx] = sx;
        g_hs[idx] = ga * sx + (float)NPIX * be;
    }
}

// ---------------- pure feature transpose: x[b,c,p] -> xT[b,p,c] ----------------
__global__ void __launch_bounds__(256) transpose_feat_kernel(
    const float* __restrict__ x, float* __restrict__ xT)
{
    __shared__ float ts[32][33];
    int b = blockIdx.z, ch0 = blockIdx.y << 5, px0 = blockIdx.x << 5;
    int tid = threadIdx.x;
    int cl = tid >> 3, f4 = tid & 7;
    size_t off = (size_t)b * CCH * NPIX + (size_t)(ch0 + cl) * NPIX + px0 + (f4 << 2);
    float4 v = *(const float4*)(x + off);
    ts[cl][(f4 << 2) + 0] = v.x;
    ts[cl][(f4 << 2) + 1] = v.y;
    ts[cl][(f4 << 2) + 2] = v.z;
    ts[cl][(f4 << 2) + 3] = v.w;
    __syncthreads();
    int pl = tid >> 3, c4 = tid & 7;
    float4 o;
    o.x = ts[(c4 << 2) + 0][pl];
    o.y = ts[(c4 << 2) + 1][pl];
    o.z = ts[(c4 << 2) + 2][pl];
    o.w = ts[(c4 << 2) + 3][pl];
    float* hp = xT + (size_t)b * NPIX * CCH + (size_t)(px0 + pl) * CCH + ch0 + (c4 << 2);
    *(float4*)hp = o;
}

// ---------------- GEMM: D = scale*A*B^T (+bias)(+resid)(*cscale), NT only ----------------
// CTA 128x128, BK=32, 4 warps (2x2), warp tile 64x64, 2 CTAs/SM.
// PREC=0: plain tf32 (m16n8k8).  PREC=1: split-bf16 2-plane, 3 products (m16n8k16).
#define A_SUB 132
#define B_SUB 66
#define ST_A 4224                 // A region (32x132 tf32 subtiles == 2 bf16 planes of 16x132)
#define ST_B 4224                 // B region
#define STAGE 8448                // words per stage
#define SMEM_SZ (2 * STAGE * 4)   // 67584 B
#define A_PLANE 2112              // bf16: one A plane (16 subtiles x 132)
#define B_PLANE 2112
#define OFF_BHI ST_A              // 4224
#define OFF_BLO (ST_A + B_PLANE)  // 6336

template<int PREC>
__global__ void __launch_bounds__(128, 2) gemm_tc(
    const float* __restrict__ A, int lda, long long sA,
    const float* __restrict__ B, int ldb, long long sB,
    float* __restrict__ D, int ldd, long long sD,
    const float* __restrict__ bias, int bias_mode, long long sBias,
    const float* __restrict__ resid,
    const float* __restrict__ cscale,
    float scale, int K, int sym, long long sKsp)
{
    extern __shared__ uint32_t smem_u[];

    int tid = threadIdx.x, wid = tid >> 5, lane = tid & 31;
    int z = blockIdx.z;
    int row0, col0;
    if (sym) {
        const int sr[10] = {0,1,1,2,2,2,3,3,3,3};
        const int sc[10] = {0,0,1,0,1,2,0,1,2,3};
        row0 = sr[blockIdx.x] << 7;
        col0 = sc[blockIdx.x] << 7;
    } else {
        row0 = blockIdx.y << 7;
        col0 = blockIdx.x << 7;
    }

    A += (size_t)z * sA + (size_t)row0 * lda;
    B += (size_t)z * sB + (size_t)col0 * ldb;
    D += (size_t)z * sD;
    if (sym) {
        A += (size_t)blockIdx.y * K;
        B += (size_t)blockIdx.y * K;
        D += (size_t)blockIdx.y * sKsp;
    }
    if (resid) resid += (size_t)z * sD;

    // staging mapping: idx = tid + 128*i -> row = idx>>3 (0..127), col = (idx&7)*4
    const int r_  = tid >> 3;            // 0..15 (base; +16 per i)
    const int c0_ = (tid & 7) << 2;      // 0..28
    const int kt4_  = c0_ >> 3;          // tf32: k8 subtile 0..3
    const int kt16_ = c0_ >> 4;          // bf16: k16 subtile 0..1
    const int kp_   = (c0_ & 15) >> 1;   // bf16: b32 pair idx {0,2,4,6}
    const int khi_  = kp_ >> 2, kpm_ = kp_ & 3;

    int offA[8], offB[8];
#pragma unroll
    for (int i = 0; i < 8; i++) {
        int row = r_ + (i << 4);         // 0..127
        int mt = row >> 4, rr = row & 15;
        if (PREC == 0) {
            int regA = (((c0_ & 7) >= 4) ? 2 : 0) + (rr >> 3);
            offA[i] = (mt * 4 + kt4_) * A_SUB + ((rr & 7) << 4) + regA;
        } else {
            int gr = rr & 7, hf = rr >> 3;
            offA[i] = (mt * 2 + kt16_) * A_SUB + (gr * 4 + kpm_) * 4 + hf + (khi_ << 1);
        }
    }
#pragma unroll
    for (int i = 0; i < 8; i++) {
        int n = r_ + (i << 4);           // 0..127
        int nt = n >> 3, nn = n & 7;
        if (PREC == 0) {
            int regB = ((c0_ & 7) >= 4) ? 1 : 0;
            offB[i] = ST_A + (nt * 4 + kt4_) * B_SUB + (nn << 3) + regB;
        } else {
            offB[i] = OFF_BHI + (nt * 2 + kt16_) * B_SUB + (nn * 4 + kpm_) * 2 + khi_;
        }
    }

    const float* aG = A + (size_t)r_ * lda + c0_;
    const float* bG = B + (size_t)r_ * ldb + c0_;
    const size_t aStep = (size_t)16 * lda;
    const size_t bStep = (size_t)16 * ldb;

    const int wm4 = (wid & 1) * 4;       // warp M group
    const int wn8 = (wid >> 1) * 8;      // warp N group

    float acc[4][8][4];
#pragma unroll
    for (int mt = 0; mt < 4; mt++)
#pragma unroll
        for (int nt = 0; nt < 8; nt++)
#pragma unroll
            for (int g = 0; g < 4; g++) acc[mt][nt][g] = 0.f;

    const int NK = K >> 5;
    float4 ra[8], rb[8];

    auto stage_load = [&](int s) {
        const float* aN = aG + (size_t)s * 32;
        const float* bN = bG + (size_t)s * 32;
#pragma unroll
        for (int i = 0; i < 8; i++) ra[i] = *(const float4*)(aN + i * aStep);
#pragma unroll
        for (int i = 0; i < 8; i++) rb[i] = *(const float4*)(bN + i * bStep);
    };

    auto stage_store = [&](uint32_t* sb) {
        if (PREC == 0) {
            float* sf = (float*)sb;
#pragma unroll
            for (int i = 0; i < 8; i++) {
                float* sa = sf + offA[i];
                sa[0]  = tf32r(ra[i].x);
                sa[4]  = tf32r(ra[i].y);
                sa[8]  = tf32r(ra[i].z);
                sa[12] = tf32r(ra[i].w);
            }
#pragma unroll
            for (int i = 0; i < 8; i++) {
                float* sp = sf + offB[i];
                sp[0] = tf32r(rb[i].x);
                sp[2] = tf32r(rb[i].y);
                sp[4] = tf32r(rb[i].z);
                sp[6] = tf32r(rb[i].w);
            }
        } else {
#pragma unroll
            for (int i = 0; i < 8; i++) {
                uint32_t h01, l01, h23, l23;
                bsplit2(ra[i].x, ra[i].y, h01, l01);
                bsplit2(ra[i].z, ra[i].w, h23, l23);
                sb[offA[i]]               = h01;
                sb[offA[i] + 4]           = h23;
                sb[A_PLANE + offA[i]]     = l01;
                sb[A_PLANE + offA[i] + 4] = l23;
            }
#pragma unroll
            for (int i = 0; i < 8; i++) {
                uint32_t h01, l01, h23, l23;
                bsplit2(rb[i].x, rb[i].y, h01, l01);
                bsplit2(rb[i].z, rb[i].w, h23, l23);
                sb[offB[i]]               = h01;
                sb[offB[i] + 2]           = h23;
                sb[B_PLANE + offB[i]]     = l01;
                sb[B_PLANE + offB[i] + 2] = l23;
            }
        }
    };

    stage_load(0);
    stage_store(smem_u);
    __syncthreads();

    for (int s = 0; s < NK; s++) {
        if (s + 1 < NK) stage_load(s + 1);
        const uint32_t* cS = smem_u + (s & 1) * STAGE;
        if (PREC == 0) {
#pragma unroll
            for (int kt = 0; kt < 4; kt++) {
                uint4 af[4]; uint2 bf[8];
#pragma unroll
                for (int mt = 0; mt < 4; mt++)
                    af[mt] = *(const uint4*)(cS + ((wm4 + mt) * 4 + kt) * A_SUB + (lane << 2));
#pragma unroll
                for (int nt = 0; nt < 8; nt++)
                    bf[nt] = *(const uint2*)(cS + ST_A + ((wn8 + nt) * 4 + kt) * B_SUB + (lane << 1));
#pragma unroll
                for (int mt = 0; mt < 4; mt++)
#pragma unroll
                    for (int nt = 0; nt < 8; nt++)
                        mma_tf32(acc[mt][nt], &af[mt].x, &bf[nt].x);
            }
        } else {
#pragma unroll
            for (int kt = 0; kt < 2; kt++) {
                uint4 af[4]; uint2 bf[8];
#pragma unroll
                for (int mt = 0; mt < 4; mt++)
                    af[mt] = *(const uint4*)(cS + ((wm4 + mt) * 2 + kt) * A_SUB + (lane << 2));
#pragma unroll
                for (int nt = 0; nt < 8; nt++)
                    bf[nt] = *(const uint2*)(cS + OFF_BHI + ((wn8 + nt) * 2 + kt) * B_SUB + (lane << 1));
#pragma unroll
                for (int mt = 0; mt < 4; mt++)
#pragma unroll
                    for (int nt = 0; nt < 8; nt++)
                        mma_bf16(acc[mt][nt], &af[mt].x, &bf[nt].x);
                {
                    uint4 al[4];
#pragma unroll
                    for (int mt = 0; mt < 4; mt++)
                        al[mt] = *(const uint4*)(cS + A_PLANE + ((wm4 + mt) * 2 + kt) * A_SUB + (lane << 2));
#pragma unroll
                    for (int mt = 0; mt < 4; mt++)
#pragma unroll
                        for (int nt = 0; nt < 8; nt++)
                            mma_bf16(acc[mt][nt], &al[mt].x, &bf[nt].x);
                }
                {
                    uint2 bl[8];
#pragma unroll
                    for (int nt = 0; nt < 8; nt++)
                        bl[nt] = *(const uint2*)(cS + OFF_BLO + ((wn8 + nt) * 2 + kt) * B_SUB + (lane << 1));
#pragma unroll
                    for (int mt = 0; mt < 4; mt++)
#pragma unroll
                        for (int nt = 0; nt < 8; nt++)
                            mma_bf16(acc[mt][nt], &af[mt].x, &bl[nt].x);
                }
            }
        }
        if (s + 1 < NK) {
            stage_store(smem_u + ((s + 1) & 1) * STAGE);
            __syncthreads();
        }
    }

    // ---- epilogue ----
    const int lane4 = lane >> 2, laneq = lane & 3;
    const int wrow = row0 + (wid & 1) * 64;
    const int wcol = col0 + (wid >> 1) * 64;
#pragma unroll
    for (int mt = 0; mt < 4; mt++) {
#pragma unroll
        for (int half = 0; half < 2; half++) {
            int r = wrow + mt * 16 + lane4 + half * 8;
            float rb_ = (bias_mode == 1) ? bias[(size_t)z * sBias + r] : 0.f;
            float* drow = D + (size_t)r * ldd + wcol;
            const float* rrow = resid ? (resid + (size_t)r * ldd + wcol) : nullptr;
#pragma unroll
            for (int nt = 0; nt < 8; nt++) {
                int c = nt * 8 + laneq * 2;
                float2 o;
                o.x = acc[mt][nt][half * 2 + 0] * scale;
                o.y = acc[mt][nt][half * 2 + 1] * scale;
                if (cscale) {
                    o.x *= cscale[(size_t)z * CCH + wcol + c];
                    o.y *= cscale[(size_t)z * CCH + wcol + c + 1];
                }
                o.x += rb_; o.y += rb_;
                if (bias_mode == 2) {
                    o.x += bias[(size_t)z * sBias + wcol + c];
                    o.y += bias[(size_t)z * sBias + wcol + c + 1];
                }
                if (rrow) { o.x += rrow[c]; o.y += rrow[c + 1]; }
                *(float2*)(drow + c) = o;
            }
        }
    }
}

// ---------------- reduce split-K Gram partials + exact GN rank-1 corrections ----------------
// computes only lower-triangle 128-tiles (tile_i >= tile_j); mirror fills the rest
__global__ void __launch_bounds__(256) reduce_g_kernel(const float* __restrict__ Gp,
                                                       float* __restrict__ G)
{
    const size_t per = (size_t)BATCH * CCH * CCH;
    int b = blockIdx.y;
    int idx = (blockIdx.x * 256 + threadIdx.x) << 2;
    int i = idx >> 9, j = idx & 511;
    if ((i >> 7) < (j >> 7)) return;
    size_t off = (size_t)b * CCH * CCH + idx;
    float4 s0 = *(const float4*)(Gp + off);
    float4 s1 = *(const float4*)(Gp + per + off);
    float4 s2 = *(const float4*)(Gp + 2 * per + off);
    float4 s3 = *(const float4*)(Gp + 3 * per + off);
    int ri = (b << 9) + i, rj = (b << 9) + j;
    float gai = g_ga[ri], hsxi = gai * g_sx[ri], bei = g_be[ri];
    float4 gaj = *(const float4*)(g_ga + rj);
    float4 bej = *(const float4*)(g_be + rj);
    float4 hsj = *(const float4*)(g_hs + rj);
    float4 o;
    o.x = gai * gaj.x * ((s0.x + s1.x) + (s2.x + s3.x)) + hsxi * bej.x + bei * hsj.x;
    o.y = gai * gaj.y * ((s0.y + s1.y) + (s2.y + s3.y)) + hsxi * bej.y + bei * hsj.y;
    o.z = gai * gaj.z * ((s0.z + s1.z) + (s2.z + s3.z)) + hsxi * bej.z + bei * hsj.z;
    o.w = gai * gaj.w * ((s0.w + s1.w) + (s2.w + s3.w)) + hsxi * bej.w + bei * hsj.w;
    *(float4*)(G + off) = o;
}

// ---------------- mirror upper-triangle 128-tiles of symmetric G ----------------
__global__ void __launch_bounds__(256) mirror_kernel(float* __restrict__ G)
{
    __shared__ float t[32][33];
    const int pr[6] = {0,0,0,1,1,2};
    const int pc[6] = {1,2,3,2,3,3};
    float* Gb = G + (size_t)blockIdx.z * CCH * CCH;
    int p = blockIdx.y;
    int sub = blockIdx.x;                 // 0..15
    int y0 = (pr[p] << 7) + ((sub >> 2) << 5);   // dest rows
    int x0 = (pc[p] << 7) + ((sub & 3) << 5);    // dest cols
    int lx = threadIdx.x & 31, ly = threadIdx.x >> 5;
#pragma unroll
    for (int ii = 0; ii < 4; ii++)
        t[ly + ii * 8][lx] = Gb[(size_t)(x0 + ly + ii * 8) * CCH + y0 + lx];
    __syncthreads();
#pragma unroll
    for (int ii = 0; ii < 4; ii++)
        Gb[(size_t)(y0 + ly + ii * 8) * CCH + x0 + lx] = t[lx][ly + ii * 8];
}

// ---------------- softmax with rank-1 bias corrections ----------------
__global__ void softmax_kernel(const float* __restrict__ S, float* __restrict__ attn,
                               const float* __restrict__ u, const float* __restrict__ w,
                               const float* __restrict__ bq, const float* __restrict__ bk,
                               float scale)
{
    int gw = (blockIdx.x * blockDim.x + threadIdx.x) >> 5;
    int lane = threadIdx.x & 31;
    if (gw >= BATCH * CCH) return;
    int b = gw >> 9, c = gw & 511;
    const float* row = S + (size_t)gw * CCH;
    float* orow = attn + (size_t)gw * CCH;
    float uc = u[(b << 9) + c], bqc = bq[c];
    float v[16];
    float m = -3.4e38f;
#pragma unroll
    for (int i = 0; i < 16; i++) {
        int d = lane + (i << 5);
        float bkd = bk[d], wd = w[(b << 9) + d];
        v[i] = scale * (row[d] + uc * bkd + bqc * wd + (float)NPIX * bqc * bkd);
        m = fmaxf(m, v[i]);
    }
#pragma unroll
    for (int o = 16; o > 0; o >>= 1) m = fmaxf(m, __shfl_xor_sync(0xffffffffu, m, o));
    float s = 0.f;
#pragma unroll
    for (int i = 0; i < 16; i++) { v[i] = __expf(v[i] - m); s += v[i]; }
#pragma unroll
    for (int o = 16; o > 0; o >>= 1) s += __shfl_xor_sync(0xffffffffu, s, o);
    float inv = 1.f / s;
#pragma unroll
    for (int i = 0; i < 16; i++) orow[lane + (i << 5)] = v[i] * inv;
}

// ---------------- 512x512 transpose (per batch z) ----------------
__global__ void __launch_bounds__(256) transpose_kernel(
    const float* __restrict__ in, float* __restrict__ out, long long sIn, long long sOut)
{
    __shared__ float t[32][33];
    int z = blockIdx.z;
    in  += (size_t)z * sIn;
    out += (size_t)z * sOut;
    int x0 = blockIdx.x << 5, y0 = blockIdx.y << 5;
    int lx = threadIdx.x & 31, ly = threadIdx.x >> 5;
#pragma unroll
    for (int i = 0; i < 4; i++)
        t[ly + i * 8][lx] = in[(size_t)(y0 + ly + i * 8) * CCH + x0 + lx];
    __syncthreads();
#pragma unroll
    for (int i = 0; i < 4; i++)
        out[(size_t)(x0 + ly + i * 8) * CCH + y0 + lx] = t[lx][ly + i * 8];
}

// ---------------- batched matvec: y[b,m] = W_b[m,:].(v_b + v2) (+bias[m]) ----------------
__global__ void matvec_kernel(const float* __restrict__ W, long long sW,
                              const float* __restrict__ v, long long sV,
                              const float* __restrict__ v2,
                              float* __restrict__ y, long long sY,
                              const float* __restrict__ bias)
{
    int b = blockIdx.y;
    int m = (blockIdx.x << 3) + (threadIdx.x >> 5);
    int lane = threadIdx.x & 31;
    const float* wr = W + (size_t)b * sW + (size_t)m * CCH;
    const float* vv = v + (size_t)b * sV;
    float s = 0.f;
    for (int k = lane; k < CCH; k += 32) {
        float vk = vv[k];
        if (v2) vk += v2[k];
        s += wr[k] * vk;
    }
#pragma unroll
    for (int o = 16; o > 0; o >>= 1) s += __shfl_xor_sync(0xffffffffu, s, o);
    if (lane == 0) y[(size_t)b * sY + m] = s + (bias ? bias[m] : 0.f);
}

__global__ void matvec_uw_kernel(const float* __restrict__ Wq, const float* __restrict__ Wk,
                                 const float* __restrict__ hs,
                                 float* __restrict__ u, float* __restrict__ w)
{
    const float* W = blockIdx.z ? Wk : Wq;
    float* y = blockIdx.z ? w : u;
    int b = blockIdx.y;
    int m = (blockIdx.x << 3) + (threadIdx.x >> 5);
    int lane = threadIdx.x & 31;
    const float* wr = W + (size_t)m * CCH;
    const float* vv = hs + (size_t)b * CCH;
    float s = 0.f;
    for (int k = lane; k < CCH; k += 32) s += wr[k] * vv[k];
#pragma unroll
    for (int o = 16; o > 0; o >>= 1) s += __shfl_xor_sync(0xffffffffu, s, o);
    if (lane == 0) y[(size_t)b * CCH + m] = s;
}

// ---------------- launch ----------------
extern "C" void kernel_launch(void* const* d_in, const int* in_sizes, int n_in,
                              void* d_out, int out_size)
{
    const float* x     = (const float*)d_in[0];
    const float* gamma = (const float*)d_in[1];
    const float* beta  = (const float*)d_in[2];
    const float* Wq    = (const float*)d_in[3];
    const float* bq    = (const float*)d_in[4];
    const float* Wk    = (const float*)d_in[5];
    const float* bk    = (const float*)d_in[6];
    const float* Wv    = (const float*)d_in[7];
    const float* bv    = (const float*)d_in[8];
    const float* Wo    = (const float*)d_in[9];
    const float* bo    = (const float*)d_in[10];
    float* out = (float*)d_out;

    float *xT, *Gp, *G, *T1, *S, *attn, *attnT, *T2, *P, *WvT;
    float *ga, *be, *hs, *u, *w, *v1, *t, *r;
    cudaGetSymbolAddress((void**)&xT,    g_xT);
    cudaGetSymbolAddress((void**)&Gp,    g_Gp);
    cudaGetSymbolAddress((void**)&G,     g_G);
    cudaGetSymbolAddress((void**)&T1,    g_T1);
    cudaGetSymbolAddress((void**)&S,     g_S);
    cudaGetSymbolAddress((void**)&attn,  g_attn);
    cudaGetSymbolAddress((void**)&attnT, g_attnT);
    cudaGetSymbolAddress((void**)&T2,    g_T2);
    cudaGetSymbolAddress((void**)&P,     g_P);
    cudaGetSymbolAddress((void**)&WvT,   g_WvT);
    cudaGetSymbolAddress((void**)&ga,    g_ga);
    cudaGetSymbolAddress((void**)&be,    g_be);
    cudaGetSymbolAddress((void**)&hs,    g_hs);
    cudaGetSymbolAddress((void**)&u,     g_u);
    cudaGetSymbolAddress((void**)&w,     g_w);
    cudaGetSymbolAddress((void**)&v1,    g_v1);
    cudaGetSymbolAddress((void**)&t,     g_t);
    cudaGetSymbolAddress((void**)&r,     g_r);

    cudaFuncSetAttribute((const void*)gemm_tc<0>, cudaFuncAttributeMaxDynamicSharedMemorySize, SMEM_SZ);
    cudaFuncSetAttribute((const void*)gemm_tc<1>, cudaFuncAttributeMaxDynamicSharedMemorySize, SMEM_SZ);

    const long long sF  = (long long)CCH * NPIX;
    const long long sAt = (long long)CCH * CCH;
    const long long sKsp = (long long)BATCH * CCH * CCH;
    const float scale = 1.0f / sqrtf((float)CCH);

    // 1) stats (ga/be/sx/hs); x transpose; bias vectors; WvT
    gn_stats_kernel<<<BATCH * 32, 256>>>(x, gamma, beta);
    transpose_feat_kernel<<<dim3(NPIX / 32, CCH / 32, BATCH), 256>>>(x, xT);
    matvec_uw_kernel<<<dim3(CCH / 8, BATCH, 2), 256>>>(Wq, Wk, hs, u, w);
    transpose_kernel<<<dim3(16, 16, 1), 256>>>(Wv, WvT, 0, 0);

    // 2) Gx = x x^T (raw Gram, sym: 10 of 16 tiles), split-K; reduce+corrections; mirror
    gemm_tc<0><<<dim3(10, KSPLIT, BATCH), 128, SMEM_SZ>>>(
        x, NPIX, sF, x, NPIX, sF, Gp, CCH, sAt,
        nullptr, 0, 0, nullptr, nullptr, 1.f, NPIX / KSPLIT, 1, sKsp);
    reduce_g_kernel<<<dim3(256, BATCH), 256>>>(Gp, G);
    mirror_kernel<<<dim3(16, 6, BATCH), 256>>>(G);

    // 3) T1 = Wq G (NT, G symmetric); S = T1 Wk^T (NT)  — split-bf16 precision
    gemm_tc<1><<<dim3(4, 4, BATCH), 128, SMEM_SZ>>>(
        Wq, CCH, 0, G, CCH, sAt, T1, CCH, sAt, nullptr, 0, 0, nullptr, nullptr, 1.f, CCH, 0, 0);
    gemm_tc<1><<<dim3(4, 4, BATCH), 128, SMEM_SZ>>>(
        T1, CCH, sAt, Wk, CCH, 0, S, CCH, sAt, nullptr, 0, 0, nullptr, nullptr, 1.f, CCH, 0, 0);

    // 4) softmax (rank-1 bias corrections); attn transpose
    softmax_kernel<<<(BATCH * CCH * 32) / 256, 256>>>(S, attn, u, w, bq, bk, scale);
    transpose_kernel<<<dim3(16, 16, BATCH), 256>>>(attn, attnT, sAt, sAt);

    // 5) T2 = Wo attn (B = attnT); P' = (T2 Wv)(B = WvT) * diag(ga)
    gemm_tc<0><<<dim3(4, 4, BATCH), 128, SMEM_SZ>>>(
        Wo, CCH, 0, attnT, CCH, sAt, T2, CCH, sAt, nullptr, 0, 0, nullptr, nullptr, 1.f, CCH, 0, 0);
    gemm_tc<0><<<dim3(4, 4, BATCH), 128, SMEM_SZ>>>(
        T2, CCH, sAt, WvT, CCH, 0, P, CCH, sAt, nullptr, 0, 0, nullptr, ga, 1.f, CCH, 0, 0);

    // 6) r = Wo (attn (Wv be + bv)) + bo
    matvec_kernel<<<dim3(CCH / 8, BATCH), 256>>>(Wv, 0, be, CCH, nullptr, v1, CCH, nullptr);
    matvec_kernel<<<dim3(CCH / 8, BATCH), 256>>>(attn, sAt, v1, CCH, bv, t, CCH, nullptr);
    matvec_kernel<<<dim3(CCH / 8, BATCH), 256>>>(Wo, 0, t, CCH, nullptr, r, CCH, bo);

    // 7) out = P' x + r + x   (NT: B = xT [4096, 512])
    gemm_tc<0><<<dim3(NPIX / 128, 4, BATCH), 128, SMEM_SZ>>>(
        P, CCH, sAt, xT, CCH, sF, out, NPIX, sF, r, 1, CCH, x, nullptr, 1.f, CCH, 0, 0);
}

// round 12
// speedup vs baseline: 1.2324x; 1.1364x over previous
#include <cuda_runtime.h>
#include <cuda_bf16.h>
#include <math.h>
#include <stdint.h>

#define BATCH 16
#define CCH   512
#define NPIX  4096
#define KSPLIT 4

// ---------------- scratch (__device__ globals; no allocation allowed) ----------------
__device__ float g_xT  [(size_t)BATCH * NPIX * CCH];
__device__ float g_Gp  [(size_t)KSPLIT * BATCH * CCH * CCH];
__device__ float g_G   [(size_t)BATCH * CCH * CCH];
__device__ float g_T1  [(size_t)BATCH * CCH * CCH];
__device__ float g_S   [(size_t)BATCH * CCH * CCH];
__device__ float g_attn[(size_t)BATCH * CCH * CCH];
__device__ float g_attnT[(size_t)BATCH * CCH * CCH];
__device__ float g_T2  [(size_t)BATCH * CCH * CCH];
__device__ float g_P   [(size_t)BATCH * CCH * CCH];
__device__ float g_WvT [(size_t)CCH * CCH];
__device__ float g_ga  [BATCH * CCH];
__device__ float g_be  [BATCH * CCH];
__device__ float g_sx  [BATCH * CCH];
__device__ float g_hs  [BATCH * CCH];
__device__ float g_u   [BATCH * CCH];
__device__ float g_w   [BATCH * CCH];
__device__ float g_v1  [BATCH * CCH];
__device__ float g_t   [BATCH * CCH];
__device__ float g_r   [BATCH * CCH];

// ---------------- helpers ----------------
__device__ __forceinline__ float tf32r(float x) {
    float y; asm("cvt.rna.tf32.f32 %0, %1;" : "=f"(y) : "f"(x)); return y;
}
__device__ __forceinline__ void bsplit2(float x0, float x1, uint32_t& hi, uint32_t& lo)
{
    __nv_bfloat16 h0 = __float2bfloat16(x0), h1 = __float2bfloat16(x1);
    float f0 = __bfloat162float(h0), f1 = __bfloat162float(h1);
    __nv_bfloat16 l0 = __float2bfloat16(x0 - f0), l1 = __float2bfloat16(x1 - f1);
    __nv_bfloat162 H(h0, h1), L(l0, l1);
    hi = *reinterpret_cast<uint32_t*>(&H);
    lo = *reinterpret_cast<uint32_t*>(&L);
}
__device__ __forceinline__ void mma_tf32(float* d, const uint32_t* a, const uint32_t* b) {
    asm volatile(
        "mma.sync.aligned.m16n8k8.row.col.f32.tf32.tf32.f32 "
        "{%0,%1,%2,%3}, {%4,%5,%6,%7}, {%8,%9}, {%0,%1,%2,%3};"
        : "+f"(d[0]), "+f"(d[1]), "+f"(d[2]), "+f"(d[3])
        : "r"(a[0]), "r"(a[1]), "r"(a[2]), "r"(a[3]), "r"(b[0]), "r"(b[1]));
}
__device__ __forceinline__ void mma_bf16(float* d, const uint32_t* a, const uint32_t* b) {
    asm volatile(
        "mma.sync.aligned.m16n8k16.row.col.f32.bf16.bf16.f32 "
        "{%0,%1,%2,%3}, {%4,%5,%6,%7}, {%8,%9}, {%0,%1,%2,%3};"
        : "+f"(d[0]), "+f"(d[1]), "+f"(d[2]), "+f"(d[3])
        : "r"(a[0]), "r"(a[1]), "r"(a[2]), "r"(a[3]), "r"(b[0]), "r"(b[1]));
}

#define A_SUB 132
#define B_SUB 66

// ---------------- GroupNorm stats: emits ga/be/sx/hs ----------------
__global__ void gn_stats_kernel(const float* __restrict__ x,
                                const float* __restrict__ gamma,
                                const float* __restrict__ beta)
{
    int bg = blockIdx.x;
    int b = bg >> 5, g = bg & 31;
    size_t base = (size_t)bg * (16 * NPIX);
    int wid = threadIdx.x >> 5, lane = threadIdx.x & 31;
    __shared__ float chs[16], chss[16];
    __shared__ float2 st_sh;

#pragma unroll
    for (int c2 = 0; c2 < 2; c2++) {
        int cl = wid * 2 + c2;
        const float4* xp = (const float4*)(x + base + (size_t)cl * NPIX);
        float s = 0.f, ss = 0.f;
        for (int i = lane; i < NPIX / 4; i += 32) {
            float4 v = xp[i];
            s  += v.x + v.y + v.z + v.w;
            ss += v.x * v.x + v.y * v.y + v.z * v.z + v.w * v.w;
        }
#pragma unroll
        for (int o = 16; o > 0; o >>= 1) {
            s  += __shfl_xor_sync(0xffffffffu, s, o);
            ss += __shfl_xor_sync(0xffffffffu, ss, o);
        }
        if (lane == 0) { chs[cl] = s; chss[cl] = ss; }
    }
    __syncthreads();
    if (threadIdx.x == 0) {
        float s = 0.f, ss = 0.f;
#pragma unroll
        for (int i = 0; i < 16; i++) { s += chs[i]; ss += chss[i]; }
        float mean = s * (1.f / (16 * NPIX));
        float var  = ss * (1.f / (16 * NPIX)) - mean * mean;
        st_sh = make_float2(mean, rsqrtf(var + 1e-6f));
    }
    __syncthreads();
    if (threadIdx.x < 16) {
        int cl = threadIdx.x, ch = g * 16 + cl;
        float2 st = st_sh;
        float ga = gamma[ch] * st.y;
        float be = beta[ch] - st.x * ga;
        float sx = chs[cl];
        int idx = (b << 9) + ch;
        g_ga[idx] = ga;
        g_be[idx] = be;
        g_sx[idx] = sx;
        g_hs[idx] = ga * sx + (float)NPIX * be;
    }
}

// ---------------- pure feature transpose: x[b,c,p] -> xT[b,p,c] ----------------
__global__ void __launch_bounds__(256) transpose_feat_kernel(
    const float* __restrict__ x, float* __restrict__ xT)
{
    __shared__ float ts[32][33];
    int b = blockIdx.z, ch0 = blockIdx.y << 5, px0 = blockIdx.x << 5;
    int tid = threadIdx.x;
    int cl = tid >> 3, f4 = tid & 7;
    size_t off = (size_t)b * CCH * NPIX + (size_t)(ch0 + cl) * NPIX + px0 + (f4 << 2);
    float4 v = *(const float4*)(x + off);
    ts[cl][(f4 << 2) + 0] = v.x;
    ts[cl][(f4 << 2) + 1] = v.y;
    ts[cl][(f4 << 2) + 2] = v.z;
    ts[cl][(f4 << 2) + 3] = v.w;
    __syncthreads();
    int pl = tid >> 3, c4 = tid & 7;
    float4 o;
    o.x = ts[(c4 << 2) + 0][pl];
    o.y = ts[(c4 << 2) + 1][pl];
    o.z = ts[(c4 << 2) + 2][pl];
    o.w = ts[(c4 << 2) + 3][pl];
    float* hp = xT + (size_t)b * NPIX * CCH + (size_t)(px0 + pl) * CCH + ch0 + (c4 << 2);
    *(float4*)hp = o;
}

// ================= gemm256: tf32 NT, CTA 256x128, 256 threads (heavies; R7-measured) =================
#define G256_AF   (64 * A_SUB)               // 8448
#define G256_BF   (64 * B_SUB)               // 4224
#define G256_STG  (G256_AF + G256_BF)        // 12672
#define SMEM256   (2 * G256_STG * 4)         // 101376 B

__global__ void __launch_bounds__(256, 1) gemm256(
    const float* __restrict__ A, int lda, long long sA,
    const float* __restrict__ B, int ldb, long long sB,
    float* __restrict__ D, int ldd, long long sD,
    const float* __restrict__ bias, int bias_mode, long long sBias,
    const float* __restrict__ resid,
    const float* __restrict__ cscale,
    float scale, int K, int sym, long long sKsp)
{
    extern __shared__ float smem[];

    int tid = threadIdx.x, wid = tid >> 5, lane = tid & 31;
    int z = blockIdx.z;
    int row0, col0;
    if (sym) {
        int t = blockIdx.x;
        row0 = (t < 2) ? 0 : 256;
        col0 = ((t < 2) ? t : (t - 2)) << 7;
    } else {
        row0 = blockIdx.y << 8;
        col0 = blockIdx.x << 7;
    }

    A += (size_t)z * sA + (size_t)row0 * lda;
    B += (size_t)z * sB + (size_t)col0 * ldb;
    D += (size_t)z * sD;
    if (sym) {
        A += (size_t)blockIdx.y * K;
        B += (size_t)blockIdx.y * K;
        D += (size_t)blockIdx.y * sKsp;
    }
    if (resid) resid += (size_t)z * sD;

    const int r_  = tid >> 3;
    const int c0_ = (tid & 7) << 2;
    const int kt_ = c0_ >> 3;
    int offA[4], offB[4];
#pragma unroll
    for (int i = 0; i < 4; i++) {
        int r = r_ + (i << 5);
        int mt = r >> 4, rr = r & 15;
        int regA = (((c0_ & 7) >= 4) ? 2 : 0) + ((rr >> 3) & 1);
        offA[i] = (mt * 4 + kt_) * A_SUB + ((rr & 7) << 4) + regA;
    }
#pragma unroll
    for (int i = 0; i < 4; i++) {
        int r = r_ + (i << 5);
        int nt = r >> 3, nn = r & 7;
        int regB = ((c0_ & 7) >= 4) ? 1 : 0;
        offB[i] = G256_AF + (nt * 4 + kt_) * B_SUB + (nn << 3) + regB;
    }
    // A needs 8 row-chunks (256 rows), B needs 4 (128 rows)
    int offA2[8];
#pragma unroll
    for (int i = 0; i < 8; i++) {
        int r = r_ + (i << 5);
        int mt = r >> 4, rr = r & 15;
        int regA = (((c0_ & 7) >= 4) ? 2 : 0) + ((rr >> 3) & 1);
        offA2[i] = (mt * 4 + kt_) * A_SUB + ((rr & 7) << 4) + regA;
    }

    const float* aG = A + (size_t)r_ * lda + c0_;
    const float* bG = B + (size_t)r_ * ldb + c0_;
    const size_t aStep = (size_t)32 * lda;
    const size_t bStep = (size_t)32 * ldb;

    const int wm4 = (wid & 3) * 4;
    const int wn8 = (wid >> 2) * 8;

    float acc[4][8][4];
#pragma unroll
    for (int mt = 0; mt < 4; mt++)
#pragma unroll
        for (int nt = 0; nt < 8; nt++)
#pragma unroll
            for (int g = 0; g < 4; g++) acc[mt][nt][g] = 0.f;

    const int NK = K >> 5;
    float4 ra[8], rb[4];

    auto stage_load = [&](int s) {
        const float* aN = aG + (size_t)s * 32;
        const float* bN = bG + (size_t)s * 32;
#pragma unroll
        for (int i = 0; i < 8; i++) ra[i] = *(const float4*)(aN + i * aStep);
#pragma unroll
        for (int i = 0; i < 4; i++) rb[i] = *(const float4*)(bN + i * bStep);
    };
    auto stage_store = [&](float* base) {
#pragma unroll
        for (int i = 0; i < 8; i++) {
            float* sa = base + offA2[i];
            sa[0]  = tf32r(ra[i].x);
            sa[4]  = tf32r(ra[i].y);
            sa[8]  = tf32r(ra[i].z);
            sa[12] = tf32r(ra[i].w);
        }
#pragma unroll
        for (int i = 0; i < 4; i++) {
            float* sb = base + offB[i];
            sb[0] = tf32r(rb[i].x);
            sb[2] = tf32r(rb[i].y);
            sb[4] = tf32r(rb[i].z);
            sb[6] = tf32r(rb[i].w);
        }
    };

    stage_load(0);
    stage_store(smem);
    __syncthreads();

    for (int s = 0; s < NK; s++) {
        if (s + 1 < NK) stage_load(s + 1);
        const float* cS = smem + (s & 1) * G256_STG;
#pragma unroll
        for (int kt = 0; kt < 4; kt++) {
            uint4 af[4]; uint2 bf[8];
#pragma unroll
            for (int mt = 0; mt < 4; mt++)
                af[mt] = *(const uint4*)(cS + ((wm4 + mt) * 4 + kt) * A_SUB + (lane << 2));
#pragma unroll
            for (int nt = 0; nt < 8; nt++)
                bf[nt] = *(const uint2*)(cS + G256_AF + ((wn8 + nt) * 4 + kt) * B_SUB + (lane << 1));
#pragma unroll
            for (int mt = 0; mt < 4; mt++)
#pragma unroll
                for (int nt = 0; nt < 8; nt++)
                    mma_tf32(acc[mt][nt], &af[mt].x, &bf[nt].x);
        }
        if (s + 1 < NK) {
            stage_store(smem + ((s + 1) & 1) * G256_STG);
            __syncthreads();
        }
    }

    const int lane4 = lane >> 2, laneq = lane & 3;
    const int wrow = row0 + (wid & 3) * 64;
    const int wcol = col0 + (wid >> 2) * 64;
#pragma unroll
    for (int mt = 0; mt < 4; mt++) {
#pragma unroll
        for (int half = 0; half < 2; half++) {
            int r = wrow + mt * 16 + lane4 + half * 8;
            float rb_ = (bias_mode == 1) ? bias[(size_t)z * sBias + r] : 0.f;
            float* drow = D + (size_t)r * ldd + wcol;
            const float* rrow = resid ? (resid + (size_t)r * ldd + wcol) : nullptr;
#pragma unroll
            for (int nt = 0; nt < 8; nt++) {
                int c = nt * 8 + laneq * 2;
                float2 o;
                o.x = acc[mt][nt][half * 2 + 0] * scale;
                o.y = acc[mt][nt][half * 2 + 1] * scale;
                if (cscale) {
                    o.x *= cscale[(size_t)z * CCH + wcol + c];
                    o.y *= cscale[(size_t)z * CCH + wcol + c + 1];
                }
                o.x += rb_; o.y += rb_;
                if (rrow) { o.x += rrow[c]; o.y += rrow[c + 1]; }
                *(float2*)(drow + c) = o;
            }
        }
    }
}

// ================= gemm128: CTA 128x128, 128 threads, 2 CTAs/SM (smalls; R11-measured) =================
// PREC=0: plain tf32.  PREC=1: split-bf16 2-plane 3-product.
#define G128_STA  4224
#define G128_STG  8448
#define SMEM128   (2 * G128_STG * 4)   // 67584 B
#define G128_APL  2112
#define G128_BPL  2112
#define G128_BHI  G128_STA
#define G128_BLO  (G128_STA + G128_BPL)

template<int PREC>
__global__ void __launch_bounds__(128, 2) gemm128(
    const float* __restrict__ A, int lda, long long sA,
    const float* __restrict__ B, int ldb, long long sB,
    float* __restrict__ D, int ldd, long long sD,
    const float* __restrict__ cscale,
    float scale, int K)
{
    extern __shared__ uint32_t smem_u[];

    int tid = threadIdx.x, wid = tid >> 5, lane = tid & 31;
    int z = blockIdx.z;
    int row0 = blockIdx.y << 7, col0 = blockIdx.x << 7;

    A += (size_t)z * sA + (size_t)row0 * lda;
    B += (size_t)z * sB + (size_t)col0 * ldb;
    D += (size_t)z * sD;

    const int r_  = tid >> 3;
    const int c0_ = (tid & 7) << 2;
    const int kt4_  = c0_ >> 3;
    const int kt16_ = c0_ >> 4;
    const int kp_   = (c0_ & 15) >> 1;
    const int khi_  = kp_ >> 2, kpm_ = kp_ & 3;

    int offA[8], offB[8];
#pragma unroll
    for (int i = 0; i < 8; i++) {
        int row = r_ + (i << 4);
        int mt = row >> 4, rr = row & 15;
        if (PREC == 0) {
            int regA = (((c0_ & 7) >= 4) ? 2 : 0) + (rr >> 3);
            offA[i] = (mt * 4 + kt4_) * A_SUB + ((rr & 7) << 4) + regA;
        } else {
            int gr = rr & 7, hf = rr >> 3;
            offA[i] = (mt * 2 + kt16_) * A_SUB + (gr * 4 + kpm_) * 4 + hf + (khi_ << 1);
        }
    }
#pragma unroll
    for (int i = 0; i < 8; i++) {
        int n = r_ + (i << 4);
        int nt = n >> 3, nn = n & 7;
        if (PREC == 0) {
            int regB = ((c0_ & 7) >= 4) ? 1 : 0;
            offB[i] = G128_STA + (nt * 4 + kt4_) * B_SUB + (nn << 3) + regB;
        } else {
            offB[i] = G128_BHI + (nt * 2 + kt16_) * B_SUB + (nn * 4 + kpm_) * 2 + khi_;
        }
    }

    const float* aG = A + (size_t)r_ * lda + c0_;
    const float* bG = B + (size_t)r_ * ldb + c0_;
    const size_t aStep = (size_t)16 * lda;
    const size_t bStep = (size_t)16 * ldb;

    const int wm4 = (wid & 1) * 4;
    const int wn8 = (wid >> 1) * 8;

    float acc[4][8][4];
#pragma unroll
    for (int mt = 0; mt < 4; mt++)
#pragma unroll
        for (int nt = 0; nt < 8; nt++)
#pragma unroll
            for (int g = 0; g < 4; g++) acc[mt][nt][g] = 0.f;

    const int NK = K >> 5;
    float4 ra[8], rb[8];

    auto stage_load = [&](int s) {
        const float* aN = aG + (size_t)s * 32;
        const float* bN = bG + (size_t)s * 32;
#pragma unroll
        for (int i = 0; i < 8; i++) ra[i] = *(const float4*)(aN + i * aStep);
#pragma unroll
        for (int i = 0; i < 8; i++) rb[i] = *(const float4*)(bN + i * bStep);
    };

    auto stage_store = [&](uint32_t* sb) {
        if (PREC == 0) {
            float* sf = (float*)sb;
#pragma unroll
            for (int i = 0; i < 8; i++) {
                float* sa = sf + offA[i];
                sa[0]  = tf32r(ra[i].x);
                sa[4]  = tf32r(ra[i].y);
                sa[8]  = tf32r(ra[i].z);
                sa[12] = tf32r(ra[i].w);
            }
#pragma unroll
            for (int i = 0; i < 8; i++) {
                float* sp = sf + offB[i];
                sp[0] = tf32r(rb[i].x);
                sp[2] = tf32r(rb[i].y);
                sp[4] = tf32r(rb[i].z);
                sp[6] = tf32r(rb[i].w);
            }
        } else {
#pragma unroll
            for (int i = 0; i < 8; i++) {
                uint32_t h01, l01, h23, l23;
                bsplit2(ra[i].x, ra[i].y, h01, l01);
                bsplit2(ra[i].z, ra[i].w, h23, l23);
                sb[offA[i]]                  = h01;
                sb[offA[i] + 4]              = h23;
                sb[G128_APL + offA[i]]       = l01;
                sb[G128_APL + offA[i] + 4]   = l23;
            }
#pragma unroll
            for (int i = 0; i < 8; i++) {
                uint32_t h01, l01, h23, l23;
                bsplit2(rb[i].x, rb[i].y, h01, l01);
                bsplit2(rb[i].z, rb[i].w, h23, l23);
                sb[offB[i]]                  = h01;
                sb[offB[i] + 2]              = h23;
                sb[G128_BPL + offB[i]]       = l01;
                sb[G128_BPL + offB[i] + 2]   = l23;
            }
        }
    };

    stage_load(0);
    stage_store(smem_u);
    __syncthreads();

    for (int s = 0; s < NK; s++) {
        if (s + 1 < NK) stage_load(s + 1);
        const uint32_t* cS = smem_u + (s & 1) * G128_STG;
        if (PREC == 0) {
#pragma unroll
            for (int kt = 0; kt < 4; kt++) {
                uint4 af[4]; uint2 bf[8];
#pragma unroll
                for (int mt = 0; mt < 4; mt++)
                    af[mt] = *(const uint4*)(cS + ((wm4 + mt) * 4 + kt) * A_SUB + (lane << 2));
#pragma unroll
                for (int nt = 0; nt < 8; nt++)
                    bf[nt] = *(const uint2*)(cS + G128_STA + ((wn8 + nt) * 4 + kt) * B_SUB + (lane << 1));
#pragma unroll
                for (int mt = 0; mt < 4; mt++)
#pragma unroll
                    for (int nt = 0; nt < 8; nt++)
                        mma_tf32(acc[mt][nt], &af[mt].x, &bf[nt].x);
            }
        } else {
#pragma unroll
            for (int kt = 0; kt < 2; kt++) {
                uint4 af[4]; uint2 bf[8];
#pragma unroll
                for (int mt = 0; mt < 4; mt++)
                    af[mt] = *(const uint4*)(cS + ((wm4 + mt) * 2 + kt) * A_SUB + (lane << 2));
#pragma unroll
                for (int nt = 0; nt < 8; nt++)
                    bf[nt] = *(const uint2*)(cS + G128_BHI + ((wn8 + nt) * 2 + kt) * B_SUB + (lane << 1));
#pragma unroll
                for (int mt = 0; mt < 4; mt++)
#pragma unroll
                    for (int nt = 0; nt < 8; nt++)
                        mma_bf16(acc[mt][nt], &af[mt].x, &bf[nt].x);
                {
                    uint4 al[4];
#pragma unroll
                    for (int mt = 0; mt < 4; mt++)
                        al[mt] = *(const uint4*)(cS + G128_APL + ((wm4 + mt) * 2 + kt) * A_SUB + (lane << 2));
#pragma unroll
                    for (int mt = 0; mt < 4; mt++)
#pragma unroll
                        for (int nt = 0; nt < 8; nt++)
                            mma_bf16(acc[mt][nt], &al[mt].x, &bf[nt].x);
                }
                {
                    uint2 bl[8];
#pragma unroll
                    for (int nt = 0; nt < 8; nt++)
                        bl[nt] = *(const uint2*)(cS + G128_BLO + ((wn8 + nt) * 2 + kt) * B_SUB + (lane << 1));
#pragma unroll
                    for (int mt = 0; mt < 4; mt++)
#pragma unroll
                        for (int nt = 0; nt < 8; nt++)
                            mma_bf16(acc[mt][nt], &af[mt].x, &bl[nt].x);
                }
            }
        }
        if (s + 1 < NK) {
            stage_store(smem_u + ((s + 1) & 1) * G128_STG);
            __syncthreads();
        }
    }

    const int lane4 = lane >> 2, laneq = lane & 3;
    const int wrow = row0 + (wid & 1) * 64;
    const int wcol = col0 + (wid >> 1) * 64;
#pragma unroll
    for (int mt = 0; mt < 4; mt++) {
#pragma unroll
        for (int half = 0; half < 2; half++) {
            int r = wrow + mt * 16 + lane4 + half * 8;
            float* drow = D + (size_t)r * ldd + wcol;
#pragma unroll
            for (int nt = 0; nt < 8; nt++) {
                int c = nt * 8 + laneq * 2;
                float2 o;
                o.x = acc[mt][nt][half * 2 + 0] * scale;
                o.y = acc[mt][nt][half * 2 + 1] * scale;
                if (cscale) {
                    o.x *= cscale[(size_t)z * CCH + wcol + c];
                    o.y *= cscale[(size_t)z * CCH + wcol + c + 1];
                }
                *(float2*)(drow + c) = o;
            }
        }
    }
}

// ---------------- reduce split-K Gram partials + exact GN rank-1 corrections ----------------
__global__ void __launch_bounds__(256) reduce_g_kernel(const float* __restrict__ Gp,
                                                       float* __restrict__ G)
{
    const size_t per = (size_t)BATCH * CCH * CCH;
    int b = blockIdx.y;
    int idx = (blockIdx.x * 256 + threadIdx.x) << 2;
    int i = idx >> 9, j = idx & 511;
    if (i < 256 && j >= 256) return;
    size_t off = (size_t)b * CCH * CCH + idx;
    float4 s0 = *(const float4*)(Gp + off);
    float4 s1 = *(const float4*)(Gp + per + off);
    float4 s2 = *(const float4*)(Gp + 2 * per + off);
    float4 s3 = *(const float4*)(Gp + 3 * per + off);
    int ri = (b << 9) + i, rj = (b << 9) + j;
    float gai = g_ga[ri], hsxi = gai * g_sx[ri], bei = g_be[ri];
    float4 gaj = *(const float4*)(g_ga + rj);
    float4 bej = *(const float4*)(g_be + rj);
    float4 hsj = *(const float4*)(g_hs + rj);
    float4 o;
    o.x = gai * gaj.x * ((s0.x + s1.x) + (s2.x + s3.x)) + hsxi * bej.x + bei * hsj.x;
    o.y = gai * gaj.y * ((s0.y + s1.y) + (s2.y + s3.y)) + hsxi * bej.y + bei * hsj.y;
    o.z = gai * gaj.z * ((s0.z + s1.z) + (s2.z + s3.z)) + hsxi * bej.z + bei * hsj.z;
    o.w = gai * gaj.w * ((s0.w + s1.w) + (s2.w + s3.w)) + hsxi * bej.w + bei * hsj.w;
    *(float4*)(G + off) = o;
}

// ---------------- mirror upper-right block of symmetric G ----------------
__global__ void __launch_bounds__(256) mirror_kernel(float* __restrict__ G)
{
    __shared__ float t[32][33];
    float* Gb = G + (size_t)blockIdx.z * CCH * CCH;
    int i0 = blockIdx.y << 5, j0 = 256 + (blockIdx.x << 5);
    int lx = threadIdx.x & 31, ly = threadIdx.x >> 5;
#pragma unroll
    for (int ii = 0; ii < 4; ii++)
        t[ly + ii * 8][lx] = Gb[(size_t)(j0 + ly + ii * 8) * CCH + i0 + lx];
    __syncthreads();
#pragma unroll
    for (int ii = 0; ii < 4; ii++)
        Gb[(size_t)(i0 + ly + ii * 8) * CCH + j0 + lx] = t[lx][ly + ii * 8];
}

// ---------------- softmax with rank-1 bias corrections + fused t = attn.(v1+bv) ----------------
__global__ void softmax_kernel(const float* __restrict__ S, float* __restrict__ attn,
                               const float* __restrict__ u, const float* __restrict__ w,
                               const float* __restrict__ bq, const float* __restrict__ bk,
                               const float* __restrict__ v1, const float* __restrict__ bv,
                               float* __restrict__ tvec, float scale)
{
    int gw = (blockIdx.x * blockDim.x + threadIdx.x) >> 5;
    int lane = threadIdx.x & 31;
    if (gw >= BATCH * CCH) return;
    int b = gw >> 9, c = gw & 511;
    const float* row = S + (size_t)gw * CCH;
    float* orow = attn + (size_t)gw * CCH;
    float uc = u[(b << 9) + c], bqc = bq[c];
    float v[16];
    float m = -3.4e38f;
#pragma unroll
    for (int i = 0; i < 16; i++) {
        int d = lane + (i << 5);
        float bkd = bk[d], wd = w[(b << 9) + d];
        v[i] = scale * (row[d] + uc * bkd + bqc * wd + (float)NPIX * bqc * bkd);
        m = fmaxf(m, v[i]);
    }
#pragma unroll
    for (int o = 16; o > 0; o >>= 1) m = fmaxf(m, __shfl_xor_sync(0xffffffffu, m, o));
    float s = 0.f;
#pragma unroll
    for (int i = 0; i < 16; i++) { v[i] = __expf(v[i] - m); s += v[i]; }
#pragma unroll
    for (int o = 16; o > 0; o >>= 1) s += __shfl_xor_sync(0xffffffffu, s, o);
    float inv = 1.f / s;
    float tdot = 0.f;
#pragma unroll
    for (int i = 0; i < 16; i++) {
        int d = lane + (i << 5);
        float av = v[i] * inv;
        orow[d] = av;
        tdot += av * (v1[(b << 9) + d] + bv[d]);
    }
#pragma unroll
    for (int o = 16; o > 0; o >>= 1) tdot += __shfl_xor_sync(0xffffffffu, tdot, o);
    if (lane == 0) tvec[gw] = tdot;
}

// ---------------- 512x512 transpose (per batch z) ----------------
__global__ void __launch_bounds__(256) transpose_kernel(
    const float* __restrict__ in, float* __restrict__ out, long long sIn, long long sOut)
{
    __shared__ float t[32][33];
    int z = blockIdx.z;
    in  += (size_t)z * sIn;
    out += (size_t)z * sOut;
    int x0 = blockIdx.x << 5, y0 = blockIdx.y << 5;
    int lx = threadIdx.x & 31, ly = threadIdx.x >> 5;
#pragma unroll
    for (int i = 0; i < 4; i++)
        t[ly + i * 8][lx] = in[(size_t)(y0 + ly + i * 8) * CCH + x0 + lx];
    __syncthreads();
#pragma unroll
    for (int i = 0; i < 4; i++)
        out[(size_t)(x0 + ly + i * 8) * CCH + y0 + lx] = t[lx][ly + i * 8];
}

// ---------------- combined u/w/v1 matvecs: z=0: u=Wq.hs; z=1: w=Wk.hs; z=2: v1=Wv.be ----------------
__global__ void matvec_uwv_kernel(const float* __restrict__ Wq, const float* __restrict__ Wk,
                                  const float* __restrict__ Wv,
                                  const float* __restrict__ hs, const float* __restrict__ be,
                                  float* __restrict__ u, float* __restrict__ w,
                                  float* __restrict__ v1)
{
    int zz = blockIdx.z;
    const float* W = (zz == 0) ? Wq : (zz == 1) ? Wk : Wv;
    const float* vec = (zz == 2) ? be : hs;
    float* y = (zz == 0) ? u : (zz == 1) ? w : v1;
    int b = blockIdx.y;
    int m = (blockIdx.x << 3) + (threadIdx.x >> 5);
    int lane = threadIdx.x & 31;
    const float* wr = W + (size_t)m * CCH;
    const float* vv = vec + (size_t)b * CCH;
    float s = 0.f;
    for (int k = lane; k < CCH; k += 32) s += wr[k] * vv[k];
#pragma unroll
    for (int o = 16; o > 0; o >>= 1) s += __shfl_xor_sync(0xffffffffu, s, o);
    if (lane == 0) y[(size_t)b * CCH + m] = s;
}

// ---------------- r = Wo.t + bo ----------------
__global__ void matvec_r_kernel(const float* __restrict__ Wo, const float* __restrict__ tvec,
                                const float* __restrict__ bo, float* __restrict__ r)
{
    int b = blockIdx.y;
    int m = (blockIdx.x << 3) + (threadIdx.x >> 5);
    int lane = threadIdx.x & 31;
    const float* wr = Wo + (size_t)m * CCH;
    const float* vv = tvec + (size_t)b * CCH;
    float s = 0.f;
    for (int k = lane; k < CCH; k += 32) s += wr[k] * vv[k];
#pragma unroll
    for (int o = 16; o > 0; o >>= 1) s += __shfl_xor_sync(0xffffffffu, s, o);
    if (lane == 0) r[(size_t)b * CCH + m] = s + bo[m];
}

// ---------------- launch ----------------
extern "C" void kernel_launch(void* const* d_in, const int* in_sizes, int n_in,
                              void* d_out, int out_size)
{
    const float* x     = (const float*)d_in[0];
    const float* gamma = (const float*)d_in[1];
    const float* beta  = (const float*)d_in[2];
    const float* Wq    = (const float*)d_in[3];
    const float* bq    = (const float*)d_in[4];
    const float* Wk    = (const float*)d_in[5];
    const float* bk    = (const float*)d_in[6];
    const float* Wv    = (const float*)d_in[7];
    const float* bv    = (const float*)d_in[8];
    const float* Wo    = (const float*)d_in[9];
    const float* bo    = (const float*)d_in[10];
    float* out = (float*)d_out;

    float *xT, *Gp, *G, *T1, *S, *attn, *attnT, *T2, *P, *WvT;
    float *ga, *be, *hs, *u, *w, *v1, *t, *r;
    cudaGetSymbolAddress((void**)&xT,    g_xT);
    cudaGetSymbolAddress((void**)&Gp,    g_Gp);
    cudaGetSymbolAddress((void**)&G,     g_G);
    cudaGetSymbolAddress((void**)&T1,    g_T1);
    cudaGetSymbolAddress((void**)&S,     g_S);
    cudaGetSymbolAddress((void**)&attn,  g_attn);
    cudaGetSymbolAddress((void**)&attnT, g_attnT);
    cudaGetSymbolAddress((void**)&T2,    g_T2);
    cudaGetSymbolAddress((void**)&P,     g_P);
    cudaGetSymbolAddress((void**)&WvT,   g_WvT);
    cudaGetSymbolAddress((void**)&ga,    g_ga);
    cudaGetSymbolAddress((void**)&be,    g_be);
    cudaGetSymbolAddress((void**)&hs,    g_hs);
    cudaGetSymbolAddress((void**)&u,     g_u);
    cudaGetSymbolAddress((void**)&w,     g_w);
    cudaGetSymbolAddress((void**)&v1,    g_v1);
    cudaGetSymbolAddress((void**)&t,     g_t);
    cudaGetSymbolAddress((void**)&r,     g_r);

    cudaFuncSetAttribute((const void*)gemm256,     cudaFuncAttributeMaxDynamicSharedMemorySize, SMEM256);
    cudaFuncSetAttribute((const void*)gemm128<0>,  cudaFuncAttributeMaxDynamicSharedMemorySize, SMEM128);
    cudaFuncSetAttribute((const void*)gemm128<1>,  cudaFuncAttributeMaxDynamicSharedMemorySize, SMEM128);

    const long long sF  = (long long)CCH * NPIX;
    const long long sAt = (long long)CCH * CCH;
    const long long sKsp = (long long)BATCH * CCH * CCH;
    const float scale = 1.0f / sqrtf((float)CCH);

    // 1) stats; x transpose; u/w/v1 matvecs; WvT
    gn_stats_kernel<<<BATCH * 32, 256>>>(x, gamma, beta);
    transpose_feat_kernel<<<dim3(NPIX / 32, CCH / 32, BATCH), 256>>>(x, xT);
    matvec_uwv_kernel<<<dim3(CCH / 8, BATCH, 3), 256>>>(Wq, Wk, Wv, hs, be, u, w, v1);
    transpose_kernel<<<dim3(16, 16, 1), 256>>>(Wv, WvT, 0, 0);

    // 2) Gx = x x^T (raw Gram, sym 6 tiles of 256x128), split-K; reduce + GN corrections; mirror
    gemm256<<<dim3(6, KSPLIT, BATCH), 256, SMEM256>>>(
        x, NPIX, sF, x, NPIX, sF, Gp, CCH, sAt,
        nullptr, 0, 0, nullptr, nullptr, 1.f, NPIX / KSPLIT, 1, sKsp);
    reduce_g_kernel<<<dim3(256, BATCH), 256>>>(Gp, G);
    mirror_kernel<<<dim3(8, 8, BATCH), 256>>>(G);

    // 3) T1 = Wq G; S = T1 Wk^T   (split-bf16 smalls, 2 CTAs/SM)
    gemm128<1><<<dim3(4, 4, BATCH), 128, SMEM128>>>(
        Wq, CCH, 0, G, CCH, sAt, T1, CCH, sAt, nullptr, 1.f, CCH);
    gemm128<1><<<dim3(4, 4, BATCH), 128, SMEM128>>>(
        T1, CCH, sAt, Wk, CCH, 0, S, CCH, sAt, nullptr, 1.f, CCH);

    // 4) softmax (rank-1 bias corrections, fused t); attn transpose
    softmax_kernel<<<(BATCH * CCH * 32) / 256, 256>>>(S, attn, u, w, bq, bk, v1, bv, t, scale);
    transpose_kernel<<<dim3(16, 16, BATCH), 256>>>(attn, attnT, sAt, sAt);

    // 5) T2 = Wo attn (B=attnT); P' = (T2 Wv)(B=WvT) * diag(ga)   (plain tf32 smalls)
    gemm128<0><<<dim3(4, 4, BATCH), 128, SMEM128>>>(
        Wo, CCH, 0, attnT, CCH, sAt, T2, CCH, sAt, nullptr, 1.f, CCH);
    gemm128<0><<<dim3(4, 4, BATCH), 128, SMEM128>>>(
        T2, CCH, sAt, WvT, CCH, 0, P, CCH, sAt, ga, 1.f, CCH);

    // 6) r = Wo t + bo
    matvec_r_kernel<<<dim3(CCH / 8, BATCH), 256>>>(Wo, t, bo, r);

    // 7) out = P' x + r + x   (heavy, 256x128)
    gemm256<<<dim3(NPIX / 128, 2, BATCH), 256, SMEM256>>>(
        P, CCH, sAt, xT, CCH, sF, out, NPIX, sF, r, 1, CCH, x, nullptr, 1.f, CCH, 0, 0);
}

// round 13
// speedup vs baseline: 1.2561x; 1.0192x over previous
#include <cuda_runtime.h>
#include <cuda_bf16.h>
#include <math.h>
#include <stdint.h>

#define BATCH 16
#define CCH   512
#define NPIX  4096
#define KSPLIT 4

// ---------------- scratch (__device__ globals; no allocation allowed) ----------------
__device__ float g_xT  [(size_t)BATCH * NPIX * CCH];
__device__ float g_Gp  [(size_t)KSPLIT * BATCH * CCH * CCH];
__device__ float g_G   [(size_t)BATCH * CCH * CCH];
__device__ float g_T1  [(size_t)BATCH * CCH * CCH];
__device__ float g_S   [(size_t)BATCH * CCH * CCH];
__device__ float g_attn[(size_t)BATCH * CCH * CCH];
__device__ float g_attnT[(size_t)BATCH * CCH * CCH];
__device__ float g_T2  [(size_t)BATCH * CCH * CCH];
__device__ float g_P   [(size_t)BATCH * CCH * CCH];
__device__ float g_WvT [(size_t)CCH * CCH];
__device__ float g_ps  [(size_t)BATCH * CCH * 128];   // per-(b,ch,pixel-tile) partial sums
__device__ float g_pss [(size_t)BATCH * CCH * 128];   // partial sum-of-squares
__device__ float g_ga  [BATCH * CCH];
__device__ float g_be  [BATCH * CCH];
__device__ float g_sx  [BATCH * CCH];
__device__ float g_hs  [BATCH * CCH];
__device__ float g_u   [BATCH * CCH];
__device__ float g_w   [BATCH * CCH];
__device__ float g_v1  [BATCH * CCH];
__device__ float g_t   [BATCH * CCH];
__device__ float g_r   [BATCH * CCH];

// ---------------- helpers ----------------
__device__ __forceinline__ float tf32r(float x) {
    float y; asm("cvt.rna.tf32.f32 %0, %1;" : "=f"(y) : "f"(x)); return y;
}
__device__ __forceinline__ void bsplit2(float x0, float x1, uint32_t& hi, uint32_t& lo)
{
    __nv_bfloat16 h0 = __float2bfloat16(x0), h1 = __float2bfloat16(x1);
    float f0 = __bfloat162float(h0), f1 = __bfloat162float(h1);
    __nv_bfloat16 l0 = __float2bfloat16(x0 - f0), l1 = __float2bfloat16(x1 - f1);
    __nv_bfloat162 H(h0, h1), L(l0, l1);
    hi = *reinterpret_cast<uint32_t*>(&H);
    lo = *reinterpret_cast<uint32_t*>(&L);
}
__device__ __forceinline__ void mma_tf32(float* d, const uint32_t* a, const uint32_t* b) {
    asm volatile(
        "mma.sync.aligned.m16n8k8.row.col.f32.tf32.tf32.f32 "
        "{%0,%1,%2,%3}, {%4,%5,%6,%7}, {%8,%9}, {%0,%1,%2,%3};"
        : "+f"(d[0]), "+f"(d[1]), "+f"(d[2]), "+f"(d[3])
        : "r"(a[0]), "r"(a[1]), "r"(a[2]), "r"(a[3]), "r"(b[0]), "r"(b[1]));
}
__device__ __forceinline__ void mma_bf16(float* d, const uint32_t* a, const uint32_t* b) {
    asm volatile(
        "mma.sync.aligned.m16n8k16.row.col.f32.bf16.bf16.f32 "
        "{%0,%1,%2,%3}, {%4,%5,%6,%7}, {%8,%9}, {%0,%1,%2,%3};"
        : "+f"(d[0]), "+f"(d[1]), "+f"(d[2]), "+f"(d[3])
        : "r"(a[0]), "r"(a[1]), "r"(a[2]), "r"(a[3]), "r"(b[0]), "r"(b[1]));
}

#define A_SUB 132
#define B_SUB 66

// ---------------- fused transpose + stats partials: x[b,c,p] -> xT[b,p,c], ps/pss ----------------
__global__ void __launch_bounds__(256) tr_stats_kernel(
    const float* __restrict__ x, float* __restrict__ xT)
{
    __shared__ float ts[32][33];
    int b = blockIdx.z, ch0 = blockIdx.y << 5, px0 = blockIdx.x << 5;
    int tid = threadIdx.x;
    int cl = tid >> 3, f4 = tid & 7;
    size_t off = (size_t)b * CCH * NPIX + (size_t)(ch0 + cl) * NPIX + px0 + (f4 << 2);
    float4 v = *(const float4*)(x + off);

    // per-channel partial sums over these 32 pixels (8-lane tree, fixed order)
    float s  = (v.x + v.y) + (v.z + v.w);
    float ss = (v.x * v.x + v.y * v.y) + (v.z * v.z + v.w * v.w);
#pragma unroll
    for (int o = 4; o > 0; o >>= 1) {
        s  += __shfl_down_sync(0xffffffffu, s, o);
        ss += __shfl_down_sync(0xffffffffu, ss, o);
    }
    if (f4 == 0) {
        size_t pidx = ((size_t)(b << 9) + ch0 + cl) * 128 + blockIdx.x;
        g_ps[pidx]  = s;
        g_pss[pidx] = ss;
    }

    ts[cl][(f4 << 2) + 0] = v.x;
    ts[cl][(f4 << 2) + 1] = v.y;
    ts[cl][(f4 << 2) + 2] = v.z;
    ts[cl][(f4 << 2) + 3] = v.w;
    __syncthreads();
    int pl = tid >> 3, c4 = tid & 7;
    float4 o;
    o.x = ts[(c4 << 2) + 0][pl];
    o.y = ts[(c4 << 2) + 1][pl];
    o.z = ts[(c4 << 2) + 2][pl];
    o.w = ts[(c4 << 2) + 3][pl];
    float* hp = xT + (size_t)b * NPIX * CCH + (size_t)(px0 + pl) * CCH + ch0 + (c4 << 2);
    *(float4*)hp = o;
}

// ---------------- finalize stats from partials: emits ga/be/sx/hs ----------------
__global__ void stats_final_kernel(const float* __restrict__ gamma,
                                   const float* __restrict__ beta)
{
    int bg = blockIdx.x;
    int b = bg >> 5, g = bg & 31;
    int wid = threadIdx.x >> 5, lane = threadIdx.x & 31;
    __shared__ float chs[16], chss[16];
    __shared__ float2 st_sh;

#pragma unroll
    for (int c2 = 0; c2 < 2; c2++) {
        int cl = wid * 2 + c2;
        int ch = g * 16 + cl;
        const float* ps  = g_ps  + ((size_t)(b << 9) + ch) * 128;
        const float* pss = g_pss + ((size_t)(b << 9) + ch) * 128;
        float s = 0.f, ss = 0.f;
#pragma unroll
        for (int i = 0; i < 4; i++) {
            s  += ps[lane + (i << 5)];
            ss += pss[lane + (i << 5)];
        }
#pragma unroll
        for (int o = 16; o > 0; o >>= 1) {
            s  += __shfl_xor_sync(0xffffffffu, s, o);
            ss += __shfl_xor_sync(0xffffffffu, ss, o);
        }
        if (lane == 0) { chs[cl] = s; chss[cl] = ss; }
    }
    __syncthreads();
    if (threadIdx.x == 0) {
        float s = 0.f, ss = 0.f;
#pragma unroll
        for (int i = 0; i < 16; i++) { s += chs[i]; ss += chss[i]; }
        float mean = s * (1.f / (16 * NPIX));
        float var  = ss * (1.f / (16 * NPIX)) - mean * mean;
        st_sh = make_float2(mean, rsqrtf(var + 1e-6f));
    }
    __syncthreads();
    if (threadIdx.x < 16) {
        int cl = threadIdx.x, ch = g * 16 + cl;
        float2 st = st_sh;
        float ga = gamma[ch] * st.y;
        float be = beta[ch] - st.x * ga;
        float sx = chs[cl];
        int idx = (b << 9) + ch;
        g_ga[idx] = ga;
        g_be[idx] = be;
        g_sx[idx] = sx;
        g_hs[idx] = ga * sx + (float)NPIX * be;
    }
}

// ================= gemm256: tf32 NT, CTA 256x128, 256 threads (heavies) =================
#define G256_AF   (64 * A_SUB)               // 8448
#define G256_BF   (64 * B_SUB)               // 4224
#define G256_STG  (G256_AF + G256_BF)        // 12672
#define SMEM256   (2 * G256_STG * 4)         // 101376 B

__global__ void __launch_bounds__(256, 1) gemm256(
    const float* __restrict__ A, int lda, long long sA,
    const float* __restrict__ B, int ldb, long long sB,
    float* __restrict__ D, int ldd, long long sD,
    const float* __restrict__ bias, int bias_mode, long long sBias,
    const float* __restrict__ resid,
    const float* __restrict__ cscale,
    float scale, int K, int sym, long long sKsp)
{
    extern __shared__ float smem[];

    int tid = threadIdx.x, wid = tid >> 5, lane = tid & 31;
    int z = blockIdx.z;
    int row0, col0;
    if (sym) {
        int t = blockIdx.x;
        row0 = (t < 2) ? 0 : 256;
        col0 = ((t < 2) ? t : (t - 2)) << 7;
    } else {
        row0 = blockIdx.y << 8;
        col0 = blockIdx.x << 7;
    }

    A += (size_t)z * sA + (size_t)row0 * lda;
    B += (size_t)z * sB + (size_t)col0 * ldb;
    D += (size_t)z * sD;
    if (sym) {
        A += (size_t)blockIdx.y * K;
        B += (size_t)blockIdx.y * K;
        D += (size_t)blockIdx.y * sKsp;
    }
    if (resid) resid += (size_t)z * sD;

    const int r_  = tid >> 3;
    const int c0_ = (tid & 7) << 2;
    const int kt_ = c0_ >> 3;
    int offA2[8], offB[4];
#pragma unroll
    for (int i = 0; i < 8; i++) {
        int r = r_ + (i << 5);
        int mt = r >> 4, rr = r & 15;
        int regA = (((c0_ & 7) >= 4) ? 2 : 0) + ((rr >> 3) & 1);
        offA2[i] = (mt * 4 + kt_) * A_SUB + ((rr & 7) << 4) + regA;
    }
#pragma unroll
    for (int i = 0; i < 4; i++) {
        int r = r_ + (i << 5);
        int nt = r >> 3, nn = r & 7;
        int regB = ((c0_ & 7) >= 4) ? 1 : 0;
        offB[i] = G256_AF + (nt * 4 + kt_) * B_SUB + (nn << 3) + regB;
    }

    const float* aG = A + (size_t)r_ * lda + c0_;
    const float* bG = B + (size_t)r_ * ldb + c0_;
    const size_t aStep = (size_t)32 * lda;
    const size_t bStep = (size_t)32 * ldb;

    const int wm4 = (wid & 3) * 4;
    const int wn8 = (wid >> 2) * 8;

    float acc[4][8][4];
#pragma unroll
    for (int mt = 0; mt < 4; mt++)
#pragma unroll
        for (int nt = 0; nt < 8; nt++)
#pragma unroll
            for (int g = 0; g < 4; g++) acc[mt][nt][g] = 0.f;

    const int NK = K >> 5;
    float4 ra[8], rb[4];

    auto stage_load = [&](int s) {
        const float* aN = aG + (size_t)s * 32;
        const float* bN = bG + (size_t)s * 32;
#pragma unroll
        for (int i = 0; i < 8; i++) ra[i] = *(const float4*)(aN + i * aStep);
#pragma unroll
        for (int i = 0; i < 4; i++) rb[i] = *(const float4*)(bN + i * bStep);
    };
    auto stage_store = [&](float* base) {
#pragma unroll
        for (int i = 0; i < 8; i++) {
            float* sa = base + offA2[i];
            sa[0]  = tf32r(ra[i].x);
            sa[4]  = tf32r(ra[i].y);
            sa[8]  = tf32r(ra[i].z);
            sa[12] = tf32r(ra[i].w);
        }
#pragma unroll
        for (int i = 0; i < 4; i++) {
            float* sb = base + offB[i];
            sb[0] = tf32r(rb[i].x);
            sb[2] = tf32r(rb[i].y);
            sb[4] = tf32r(rb[i].z);
            sb[6] = tf32r(rb[i].w);
        }
    };

    stage_load(0);
    stage_store(smem);
    __syncthreads();

    for (int s = 0; s < NK; s++) {
        if (s + 1 < NK) stage_load(s + 1);
        const float* cS = smem + (s & 1) * G256_STG;
#pragma unroll
        for (int kt = 0; kt < 4; kt++) {
            uint4 af[4]; uint2 bf[8];
#pragma unroll
            for (int mt = 0; mt < 4; mt++)
                af[mt] = *(const uint4*)(cS + ((wm4 + mt) * 4 + kt) * A_SUB + (lane << 2));
#pragma unroll
            for (int nt = 0; nt < 8; nt++)
                bf[nt] = *(const uint2*)(cS + G256_AF + ((wn8 + nt) * 4 + kt) * B_SUB + (lane << 1));
#pragma unroll
            for (int mt = 0; mt < 4; mt++)
#pragma unroll
                for (int nt = 0; nt < 8; nt++)
                    mma_tf32(acc[mt][nt], &af[mt].x, &bf[nt].x);
        }
        if (s + 1 < NK) {
            stage_store(smem + ((s + 1) & 1) * G256_STG);
            __syncthreads();
        }
    }

    const int lane4 = lane >> 2, laneq = lane & 3;
    const int wrow = row0 + (wid & 3) * 64;
    const int wcol = col0 + (wid >> 2) * 64;
#pragma unroll
    for (int mt = 0; mt < 4; mt++) {
#pragma unroll
        for (int half = 0; half < 2; half++) {
            int r = wrow + mt * 16 + lane4 + half * 8;
            float rb_ = (bias_mode == 1) ? bias[(size_t)z * sBias + r] : 0.f;
            float* drow = D + (size_t)r * ldd + wcol;
            const float* rrow = resid ? (resid + (size_t)r * ldd + wcol) : nullptr;
#pragma unroll
            for (int nt = 0; nt < 8; nt++) {
                int c = nt * 8 + laneq * 2;
                float2 o;
                o.x = acc[mt][nt][half * 2 + 0] * scale;
                o.y = acc[mt][nt][half * 2 + 1] * scale;
                if (cscale) {
                    o.x *= cscale[(size_t)z * CCH + wcol + c];
                    o.y *= cscale[(size_t)z * CCH + wcol + c + 1];
                }
                o.x += rb_; o.y += rb_;
                if (rrow) { o.x += rrow[c]; o.y += rrow[c + 1]; }
                *(float2*)(drow + c) = o;
            }
        }
    }
}

// ================= gemm128: CTA 128x128, 128 threads, 2 CTAs/SM (smalls) =================
#define G128_STA  4224
#define G128_STG  8448
#define SMEM128   (2 * G128_STG * 4)   // 67584 B
#define G128_APL  2112
#define G128_BPL  2112
#define G128_BHI  G128_STA
#define G128_BLO  (G128_STA + G128_BPL)

template<int PREC>
__global__ void __launch_bounds__(128, 2) gemm128(
    const float* __restrict__ A, int lda, long long sA,
    const float* __restrict__ B, int ldb, long long sB,
    float* __restrict__ D, int ldd, long long sD,
    const float* __restrict__ cscale,
    float scale, int K)
{
    extern __shared__ uint32_t smem_u[];

    int tid = threadIdx.x, wid = tid >> 5, lane = tid & 31;
    int z = blockIdx.z;
    int row0 = blockIdx.y << 7, col0 = blockIdx.x << 7;

    A += (size_t)z * sA + (size_t)row0 * lda;
    B += (size_t)z * sB + (size_t)col0 * ldb;
    D += (size_t)z * sD;

    const int r_  = tid >> 3;
    const int c0_ = (tid & 7) << 2;
    const int kt4_  = c0_ >> 3;
    const int kt16_ = c0_ >> 4;
    const int kp_   = (c0_ & 15) >> 1;
    const int khi_  = kp_ >> 2, kpm_ = kp_ & 3;

    int offA[8], offB[8];
#pragma unroll
    for (int i = 0; i < 8; i++) {
        int row = r_ + (i << 4);
        int mt = row >> 4, rr = row & 15;
        if (PREC == 0) {
            int regA = (((c0_ & 7) >= 4) ? 2 : 0) + (rr >> 3);
            offA[i] = (mt * 4 + kt4_) * A_SUB + ((rr & 7) << 4) + regA;
        } else {
            int gr = rr & 7, hf = rr >> 3;
            offA[i] = (mt * 2 + kt16_) * A_SUB + (gr * 4 + kpm_) * 4 + hf + (khi_ << 1);
        }
    }
#pragma unroll
    for (int i = 0; i < 8; i++) {
        int n = r_ + (i << 4);
        int nt = n >> 3, nn = n & 7;
        if (PREC == 0) {
            int regB = ((c0_ & 7) >= 4) ? 1 : 0;
            offB[i] = G128_STA + (nt * 4 + kt4_) * B_SUB + (nn << 3) + regB;
        } else {
            offB[i] = G128_BHI + (nt * 2 + kt16_) * B_SUB + (nn * 4 + kpm_) * 2 + khi_;
        }
    }

    const float* aG = A + (size_t)r_ * lda + c0_;
    const float* bG = B + (size_t)r_ * ldb + c0_;
    const size_t aStep = (size_t)16 * lda;
    const size_t bStep = (size_t)16 * ldb;

    const int wm4 = (wid & 1) * 4;
    const int wn8 = (wid >> 1) * 8;

    float acc[4][8][4];
#pragma unroll
    for (int mt = 0; mt < 4; mt++)
#pragma unroll
        for (int nt = 0; nt < 8; nt++)
#pragma unroll
            for (int g = 0; g < 4; g++) acc[mt][nt][g] = 0.f;

    const int NK = K >> 5;
    float4 ra[8], rb[8];

    auto stage_load = [&](int s) {
        const float* aN = aG + (size_t)s * 32;
        const float* bN = bG + (size_t)s * 32;
#pragma unroll
        for (int i = 0; i < 8; i++) ra[i] = *(const float4*)(aN + i * aStep);
#pragma unroll
        for (int i = 0; i < 8; i++) rb[i] = *(const float4*)(bN + i * bStep);
    };

    auto stage_store = [&](uint32_t* sb) {
        if (PREC == 0) {
            float* sf = (float*)sb;
#pragma unroll
            for (int i = 0; i < 8; i++) {
                float* sa = sf + offA[i];
                sa[0]  = tf32r(ra[i].x);
                sa[4]  = tf32r(ra[i].y);
                sa[8]  = tf32r(ra[i].z);
                sa[12] = tf32r(ra[i].w);
            }
#pragma unroll
            for (int i = 0; i < 8; i++) {
                float* sp = sf + offB[i];
                sp[0] = tf32r(rb[i].x);
                sp[2] = tf32r(rb[i].y);
                sp[4] = tf32r(rb[i].z);
                sp[6] = tf32r(rb[i].w);
            }
        } else {
#pragma unroll
            for (int i = 0; i < 8; i++) {
                uint32_t h01, l01, h23, l23;
                bsplit2(ra[i].x, ra[i].y, h01, l01);
                bsplit2(ra[i].z, ra[i].w, h23, l23);
                sb[offA[i]]                  = h01;
                sb[offA[i] + 4]              = h23;
                sb[G128_APL + offA[i]]       = l01;
                sb[G128_APL + offA[i] + 4]   = l23;
            }
#pragma unroll
            for (int i = 0; i < 8; i++) {
                uint32_t h01, l01, h23, l23;
                bsplit2(rb[i].x, rb[i].y, h01, l01);
                bsplit2(rb[i].z, rb[i].w, h23, l23);
                sb[offB[i]]                  = h01;
                sb[offB[i] + 2]              = h23;
                sb[G128_BPL + offB[i]]       = l01;
                sb[G128_BPL + offB[i] + 2]   = l23;
            }
        }
    };

    stage_load(0);
    stage_store(smem_u);
    __syncthreads();

    for (int s = 0; s < NK; s++) {
        if (s + 1 < NK) stage_load(s + 1);
        const uint32_t* cS = smem_u + (s & 1) * G128_STG;
        if (PREC == 0) {
#pragma unroll
            for (int kt = 0; kt < 4; kt++) {
                uint4 af[4]; uint2 bf[8];
#pragma unroll
                for (int mt = 0; mt < 4; mt++)
                    af[mt] = *(const uint4*)(cS + ((wm4 + mt) * 4 + kt) * A_SUB + (lane << 2));
#pragma unroll
                for (int nt = 0; nt < 8; nt++)
                    bf[nt] = *(const uint2*)(cS + G128_STA + ((wn8 + nt) * 4 + kt) * B_SUB + (lane << 1));
#pragma unroll
                for (int mt = 0; mt < 4; mt++)
#pragma unroll
                    for (int nt = 0; nt < 8; nt++)
                        mma_tf32(acc[mt][nt], &af[mt].x, &bf[nt].x);
            }
        } else {
#pragma unroll
            for (int kt = 0; kt < 2; kt++) {
                uint4 af[4]; uint2 bf[8];
#pragma unroll
                for (int mt = 0; mt < 4; mt++)
                    af[mt] = *(const uint4*)(cS + ((wm4 + mt) * 2 + kt) * A_SUB + (lane << 2));
#pragma unroll
                for (int nt = 0; nt < 8; nt++)
                    bf[nt] = *(const uint2*)(cS + G128_BHI + ((wn8 + nt) * 2 + kt) * B_SUB + (lane << 1));
#pragma unroll
                for (int mt = 0; mt < 4; mt++)
#pragma unroll
                    for (int nt = 0; nt < 8; nt++)
                        mma_bf16(acc[mt][nt], &af[mt].x, &bf[nt].x);
                {
                    uint4 al[4];
#pragma unroll
                    for (int mt = 0; mt < 4; mt++)
                        al[mt] = *(const uint4*)(cS + G128_APL + ((wm4 + mt) * 2 + kt) * A_SUB + (lane << 2));
#pragma unroll
                    for (int mt = 0; mt < 4; mt++)
#pragma unroll
                        for (int nt = 0; nt < 8; nt++)
                            mma_bf16(acc[mt][nt], &al[mt].x, &bf[nt].x);
                }
                {
                    uint2 bl[8];
#pragma unroll
                    for (int nt = 0; nt < 8; nt++)
                        bl[nt] = *(const uint2*)(cS + G128_BLO + ((wn8 + nt) * 2 + kt) * B_SUB + (lane << 1));
#pragma unroll
                    for (int mt = 0; mt < 4; mt++)
#pragma unroll
                        for (int nt = 0; nt < 8; nt++)
                            mma_bf16(acc[mt][nt], &af[mt].x, &bl[nt].x);
                }
            }
        }
        if (s + 1 < NK) {
            stage_store(smem_u + ((s + 1) & 1) * G128_STG);
            __syncthreads();
        }
    }

    const int lane4 = lane >> 2, laneq = lane & 3;
    const int wrow = row0 + (wid & 1) * 64;
    const int wcol = col0 + (wid >> 1) * 64;
#pragma unroll
    for (int mt = 0; mt < 4; mt++) {
#pragma unroll
        for (int half = 0; half < 2; half++) {
            int r = wrow + mt * 16 + lane4 + half * 8;
            float* drow = D + (size_t)r * ldd + wcol;
#pragma unroll
            for (int nt = 0; nt < 8; nt++) {
                int c = nt * 8 + laneq * 2;
                float2 o;
                o.x = acc[mt][nt][half * 2 + 0] * scale;
                o.y = acc[mt][nt][half * 2 + 1] * scale;
                if (cscale) {
                    o.x *= cscale[(size_t)z * CCH + wcol + c];
                    o.y *= cscale[(size_t)z * CCH + wcol + c + 1];
                }
                *(float2*)(drow + c) = o;
            }
        }
    }
}

// ---------------- reduce split-K Gram partials + exact GN rank-1 corrections ----------------
__global__ void __launch_bounds__(256) reduce_g_kernel(const float* __restrict__ Gp,
                                                       float* __restrict__ G)
{
    const size_t per = (size_t)BATCH * CCH * CCH;
    int b = blockIdx.y;
    int idx = (blockIdx.x * 256 + threadIdx.x) << 2;
    int i = idx >> 9, j = idx & 511;
    if (i < 256 && j >= 256) return;
    size_t off = (size_t)b * CCH * CCH + idx;
    float4 s0 = *(const float4*)(Gp + off);
    float4 s1 = *(const float4*)(Gp + per + off);
    float4 s2 = *(const float4*)(Gp + 2 * per + off);
    float4 s3 = *(const float4*)(Gp + 3 * per + off);
    int ri = (b << 9) + i, rj = (b << 9) + j;
    float gai = g_ga[ri], hsxi = gai * g_sx[ri], bei = g_be[ri];
    float4 gaj = *(const float4*)(g_ga + rj);
    float4 bej = *(const float4*)(g_be + rj);
    float4 hsj = *(const float4*)(g_hs + rj);
    float4 o;
    o.x = gai * gaj.x * ((s0.x + s1.x) + (s2.x + s3.x)) + hsxi * bej.x + bei * hsj.x;
    o.y = gai * gaj.y * ((s0.y + s1.y) + (s2.y + s3.y)) + hsxi * bej.y + bei * hsj.y;
    o.z = gai * gaj.z * ((s0.z + s1.z) + (s2.z + s3.z)) + hsxi * bej.z + bei * hsj.z;
    o.w = gai * gaj.w * ((s0.w + s1.w) + (s2.w + s3.w)) + hsxi * bej.w + bei * hsj.w;
    *(float4*)(G + off) = o;
}

// ---------------- mirror upper-right block of symmetric G ----------------
__global__ void __launch_bounds__(256) mirror_kernel(float* __restrict__ G)
{
    __shared__ float t[32][33];
    float* Gb = G + (size_t)blockIdx.z * CCH * CCH;
    int i0 = blockIdx.y << 5, j0 = 256 + (blockIdx.x << 5);
    int lx = threadIdx.x & 31, ly = threadIdx.x >> 5;
#pragma unroll
    for (int ii = 0; ii < 4; ii++)
        t[ly + ii * 8][lx] = Gb[(size_t)(j0 + ly + ii * 8) * CCH + i0 + lx];
    __syncthreads();
#pragma unroll
    for (int ii = 0; ii < 4; ii++)
        Gb[(size_t)(i0 + ly + ii * 8) * CCH + j0 + lx] = t[lx][ly + ii * 8];
}

// ---------------- softmax with rank-1 bias corrections + fused t = attn.(v1+bv) ----------------
__global__ void softmax_kernel(const float* __restrict__ S, float* __restrict__ attn,
                               const float* __restrict__ u, const float* __restrict__ w,
                               const float* __restrict__ bq, const float* __restrict__ bk,
                               const float* __restrict__ v1, const float* __restrict__ bv,
                               float* __restrict__ tvec, float scale)
{
    int gw = (blockIdx.x * blockDim.x + threadIdx.x) >> 5;
    int lane = threadIdx.x & 31;
    if (gw >= BATCH * CCH) return;
    int b = gw >> 9, c = gw & 511;
    const float* row = S + (size_t)gw * CCH;
    float* orow = attn + (size_t)gw * CCH;
    float uc = u[(b << 9) + c], bqc = bq[c];
    float v[16];
    float m = -3.4e38f;
#pragma unroll
    for (int i = 0; i < 16; i++) {
        int d = lane + (i << 5);
        float bkd = bk[d], wd = w[(b << 9) + d];
        v[i] = scale * (row[d] + uc * bkd + bqc * wd + (float)NPIX * bqc * bkd);
        m = fmaxf(m, v[i]);
    }
#pragma unroll
    for (int o = 16; o > 0; o >>= 1) m = fmaxf(m, __shfl_xor_sync(0xffffffffu, m, o));
    float s = 0.f;
#pragma unroll
    for (int i = 0; i < 16; i++) { v[i] = __expf(v[i] - m); s += v[i]; }
#pragma unroll
    for (int o = 16; o > 0; o >>= 1) s += __shfl_xor_sync(0xffffffffu, s, o);
    float inv = 1.f / s;
    float tdot = 0.f;
#pragma unroll
    for (int i = 0; i < 16; i++) {
        int d = lane + (i << 5);
        float av = v[i] * inv;
        orow[d] = av;
        tdot += av * (v1[(b << 9) + d] + bv[d]);
    }
#pragma unroll
    for (int o = 16; o > 0; o >>= 1) tdot += __shfl_xor_sync(0xffffffffu, tdot, o);
    if (lane == 0) tvec[gw] = tdot;
}

// ---------------- 512x512 transpose (per batch z) ----------------
__global__ void __launch_bounds__(256) transpose_kernel(
    const float* __restrict__ in, float* __restrict__ out, long long sIn, long long sOut)
{
    __shared__ float t[32][33];
    int z = blockIdx.z;
    in  += (size_t)z * sIn;
    out += (size_t)z * sOut;
    int x0 = blockIdx.x << 5, y0 = blockIdx.y << 5;
    int lx = threadIdx.x & 31, ly = threadIdx.x >> 5;
#pragma unroll
    for (int i = 0; i < 4; i++)
        t[ly + i * 8][lx] = in[(size_t)(y0 + ly + i * 8) * CCH + x0 + lx];
    __syncthreads();
#pragma unroll
    for (int i = 0; i < 4; i++)
        out[(size_t)(x0 + ly + i * 8) * CCH + y0 + lx] = t[lx][ly + i * 8];
}

// ---------------- combined u/w/v1 matvecs: z=0: u=Wq.hs; z=1: w=Wk.hs; z=2: v1=Wv.be ----------------
__global__ void matvec_uwv_kernel(const float* __restrict__ Wq, const float* __restrict__ Wk,
                                  const float* __restrict__ Wv,
                                  const float* __restrict__ hs, const float* __restrict__ be,
                                  float* __restrict__ u, float* __restrict__ w,
                                  float* __restrict__ v1)
{
    int zz = blockIdx.z;
    const float* W = (zz == 0) ? Wq : (zz == 1) ? Wk : Wv;
    const float* vec = (zz == 2) ? be : hs;
    float* y = (zz == 0) ? u : (zz == 1) ? w : v1;
    int b = blockIdx.y;
    int m = (blockIdx.x << 3) + (threadIdx.x >> 5);
    int lane = threadIdx.x & 31;
    const float* wr = W + (size_t)m * CCH;
    const float* vv = vec + (size_t)b * CCH;
    float s = 0.f;
    for (int k = lane; k < CCH; k += 32) s += wr[k] * vv[k];
#pragma unroll
    for (int o = 16; o > 0; o >>= 1) s += __shfl_xor_sync(0xffffffffu, s, o);
    if (lane == 0) y[(size_t)b * CCH + m] = s;
}

// ---------------- r = Wo.t + bo ----------------
__global__ void matvec_r_kernel(const float* __restrict__ Wo, const float* __restrict__ tvec,
                                const float* __restrict__ bo, float* __restrict__ r)
{
    int b = blockIdx.y;
    int m = (blockIdx.x << 3) + (threadIdx.x >> 5);
    int lane = threadIdx.x & 31;
    const float* wr = Wo + (size_t)m * CCH;
    const float* vv = tvec + (size_t)b * CCH;
    float s = 0.f;
    for (int k = lane; k < CCH; k += 32) s += wr[k] * vv[k];
#pragma unroll
    for (int o = 16; o > 0; o >>= 1) s += __shfl_xor_sync(0xffffffffu, s, o);
    if (lane == 0) r[(size_t)b * CCH + m] = s + bo[m];
}

// ---------------- launch ----------------
extern "C" void kernel_launch(void* const* d_in, const int* in_sizes, int n_in,
                              void* d_out, int out_size)
{
    const float* x     = (const float*)d_in[0];
    const float* gamma = (const float*)d_in[1];
    const float* beta  = (const float*)d_in[2];
    const float* Wq    = (const float*)d_in[3];
    const float* bq    = (const float*)d_in[4];
    const float* Wk    = (const float*)d_in[5];
    const float* bk    = (const float*)d_in[6];
    const float* Wv    = (const float*)d_in[7];
    const float* bv    = (const float*)d_in[8];
    const float* Wo    = (const float*)d_in[9];
    const float* bo    = (const float*)d_in[10];
    float* out = (float*)d_out;

    float *xT, *Gp, *G, *T1, *S, *attn, *attnT, *T2, *P, *WvT;
    float *ga, *be, *hs, *u, *w, *v1, *t, *r;
    cudaGetSymbolAddress((void**)&xT,    g_xT);
    cudaGetSymbolAddress((void**)&Gp,    g_Gp);
    cudaGetSymbolAddress((void**)&G,     g_G);
    cudaGetSymbolAddress((void**)&T1,    g_T1);
    cudaGetSymbolAddress((void**)&S,     g_S);
    cudaGetSymbolAddress((void**)&attn,  g_attn);
    cudaGetSymbolAddress((void**)&attnT, g_attnT);
    cudaGetSymbolAddress((void**)&T2,    g_T2);
    cudaGetSymbolAddress((void**)&P,     g_P);
    cudaGetSymbolAddress((void**)&WvT,   g_WvT);
    cudaGetSymbolAddress((void**)&ga,    g_ga);
    cudaGetSymbolAddress((void**)&be,    g_be);
    cudaGetSymbolAddress((void**)&hs,    g_hs);
    cudaGetSymbolAddress((void**)&u,     g_u);
    cudaGetSymbolAddress((void**)&w,     g_w);
    cudaGetSymbolAddress((void**)&v1,    g_v1);
    cudaGetSymbolAddress((void**)&t,     g_t);
    cudaGetSymbolAddress((void**)&r,     g_r);

    cudaFuncSetAttribute((const void*)gemm256,     cudaFuncAttributeMaxDynamicSharedMemorySize, SMEM256);
    cudaFuncSetAttribute((const void*)gemm128<0>,  cudaFuncAttributeMaxDynamicSharedMemorySize, SMEM128);
    cudaFuncSetAttribute((const void*)gemm128<1>,  cudaFuncAttributeMaxDynamicSharedMemorySize, SMEM128);

    const long long sF  = (long long)CCH * NPIX;
    const long long sAt = (long long)CCH * CCH;
    const long long sKsp = (long long)BATCH * CCH * CCH;
    const float scale = 1.0f / sqrtf((float)CCH);

    // 1) fused transpose + stats partials; finalize; u/w/v1 matvecs; WvT
    tr_stats_kernel<<<dim3(NPIX / 32, CCH / 32, BATCH), 256>>>(x, xT);
    stats_final_kernel<<<BATCH * 32, 256>>>(gamma, beta);
    matvec_uwv_kernel<<<dim3(CCH / 8, BATCH, 3), 256>>>(Wq, Wk, Wv, hs, be, u, w, v1);
    transpose_kernel<<<dim3(16, 16, 1), 256>>>(Wv, WvT, 0, 0);

    // 2) Gx = x x^T (raw Gram, sym 6 tiles of 256x128), split-K; reduce + GN corrections; mirror
    gemm256<<<dim3(6, KSPLIT, BATCH), 256, SMEM256>>>(
        x, NPIX, sF, x, NPIX, sF, Gp, CCH, sAt,
        nullptr, 0, 0, nullptr, nullptr, 1.f, NPIX / KSPLIT, 1, sKsp);
    reduce_g_kernel<<<dim3(256, BATCH), 256>>>(Gp, G);
    mirror_kernel<<<dim3(8, 8, BATCH), 256>>>(G);

    // 3) T1 = Wq G; S = T1 Wk^T   (split-bf16 smalls, 2 CTAs/SM)
    gemm128<1><<<dim3(4, 4, BATCH), 128, SMEM128>>>(
        Wq, CCH, 0, G, CCH, sAt, T1, CCH, sAt, nullptr, 1.f, CCH);
    gemm128<1><<<dim3(4, 4, BATCH), 128, SMEM128>>>(
        T1, CCH, sAt, Wk, CCH, 0, S, CCH, sAt, nullptr, 1.f, CCH);

    // 4) softmax (rank-1 bias corrections, fused t); attn transpose
    softmax_kernel<<<(BATCH * CCH * 32) / 256, 256>>>(S, attn, u, w, bq, bk, v1, bv, t, scale);
    transpose_kernel<<<dim3(16, 16, BATCH), 256>>>(attn, attnT, sAt, sAt);

    // 5) T2 = Wo attn (B=attnT); P' = (T2 Wv)(B=WvT) * diag(ga)   (plain tf32 smalls)
    gemm128<0><<<dim3(4, 4, BATCH), 128, SMEM128>>>(
        Wo, CCH, 0, attnT, CCH, sAt, T2, CCH, sAt, nullptr, 1.f, CCH);
    gemm128<0><<<dim3(4, 4, BATCH), 128, SMEM128>>>(
        T2, CCH, sAt, WvT, CCH, 0, P, CCH, sAt, ga, 1.f, CCH);

    // 6) r = Wo t + bo
    matvec_r_kernel<<<dim3(CCH / 8, BATCH), 256>>>(Wo, t, bo, r);

    // 7) out = P' x + r + x   (heavy, 256x128)
    gemm256<<<dim3(NPIX / 128, 2, BATCH), 256, SMEM256>>>(
        P, CCH, sAt, xT, CCH, sF, out, NPIX, sF, r, 1, CCH, x, nullptr, 1.f, CCH, 0, 0);
}

// round 14
// speedup vs baseline: 1.3043x; 1.0384x over previous
#include <cuda_runtime.h>
#include <cuda_bf16.h>
#include <math.h>
#include <stdint.h>

#define BATCH 16
#define CCH   512
#define NPIX  4096
#define KSPLIT 4

// ---------------- scratch (__device__ globals; no allocation allowed) ----------------
__device__ float g_xT  [(size_t)BATCH * NPIX * CCH];
__device__ float g_Gp  [(size_t)KSPLIT * BATCH * CCH * CCH];
__device__ float g_G   [(size_t)BATCH * CCH * CCH];
__device__ float g_T1  [(size_t)BATCH * CCH * CCH];
__device__ float g_S   [(size_t)BATCH * CCH * CCH];
__device__ float g_attn[(size_t)BATCH * CCH * CCH];
__device__ float g_attnT[(size_t)BATCH * CCH * CCH];
__device__ float g_T2  [(size_t)BATCH * CCH * CCH];
__device__ float g_P   [(size_t)BATCH * CCH * CCH];
__device__ float g_WvT [(size_t)CCH * CCH];
__device__ float g_ps  [(size_t)BATCH * CCH * 128];
__device__ float g_pss [(size_t)BATCH * CCH * 128];
__device__ float g_ga  [BATCH * CCH];
__device__ float g_be  [BATCH * CCH];
__device__ float g_sx  [BATCH * CCH];
__device__ float g_hs  [BATCH * CCH];
__device__ float g_u   [BATCH * CCH];
__device__ float g_w   [BATCH * CCH];
__device__ float g_v1  [BATCH * CCH];
__device__ float g_t   [BATCH * CCH];
__device__ float g_r   [BATCH * CCH];

// ---------------- helpers ----------------
__device__ __forceinline__ float tf32r(float x) {
    float y; asm("cvt.rna.tf32.f32 %0, %1;" : "=f"(y) : "f"(x)); return y;
}
__device__ __forceinline__ void bsplit2(float x0, float x1, uint32_t& hi, uint32_t& lo)
{
    __nv_bfloat16 h0 = __float2bfloat16(x0), h1 = __float2bfloat16(x1);
    float f0 = __bfloat162float(h0), f1 = __bfloat162float(h1);
    __nv_bfloat16 l0 = __float2bfloat16(x0 - f0), l1 = __float2bfloat16(x1 - f1);
    __nv_bfloat162 H(h0, h1), L(l0, l1);
    hi = *reinterpret_cast<uint32_t*>(&H);
    lo = *reinterpret_cast<uint32_t*>(&L);
}
__device__ __forceinline__ void mma_tf32(float* d, const uint32_t* a, const uint32_t* b) {
    asm volatile(
        "mma.sync.aligned.m16n8k8.row.col.f32.tf32.tf32.f32 "
        "{%0,%1,%2,%3}, {%4,%5,%6,%7}, {%8,%9}, {%0,%1,%2,%3};"
        : "+f"(d[0]), "+f"(d[1]), "+f"(d[2]), "+f"(d[3])
        : "r"(a[0]), "r"(a[1]), "r"(a[2]), "r"(a[3]), "r"(b[0]), "r"(b[1]));
}
__device__ __forceinline__ void mma_bf16(float* d, const uint32_t* a, const uint32_t* b) {
    asm volatile(
        "mma.sync.aligned.m16n8k16.row.col.f32.bf16.bf16.f32 "
        "{%0,%1,%2,%3}, {%4,%5,%6,%7}, {%8,%9}, {%0,%1,%2,%3};"
        : "+f"(d[0]), "+f"(d[1]), "+f"(d[2]), "+f"(d[3])
        : "r"(a[0]), "r"(a[1]), "r"(a[2]), "r"(a[3]), "r"(b[0]), "r"(b[1]));
}

#define A_SUB 132
#define B_SUB 66

// ---------------- fused transpose + stats partials ----------------
__global__ void __launch_bounds__(256) tr_stats_kernel(
    const float* __restrict__ x, float* __restrict__ xT)
{
    __shared__ float ts[32][33];
    int b = blockIdx.z, ch0 = blockIdx.y << 5, px0 = blockIdx.x << 5;
    int tid = threadIdx.x;
    int cl = tid >> 3, f4 = tid & 7;
    size_t off = (size_t)b * CCH * NPIX + (size_t)(ch0 + cl) * NPIX + px0 + (f4 << 2);
    float4 v = *(const float4*)(x + off);

    float s  = (v.x + v.y) + (v.z + v.w);
    float ss = (v.x * v.x + v.y * v.y) + (v.z * v.z + v.w * v.w);
#pragma unroll
    for (int o = 4; o > 0; o >>= 1) {
        s  += __shfl_down_sync(0xffffffffu, s, o);
        ss += __shfl_down_sync(0xffffffffu, ss, o);
    }
    if (f4 == 0) {
        size_t pidx = ((size_t)(b << 9) + ch0 + cl) * 128 + blockIdx.x;
        g_ps[pidx]  = s;
        g_pss[pidx] = ss;
    }

    ts[cl][(f4 << 2) + 0] = v.x;
    ts[cl][(f4 << 2) + 1] = v.y;
    ts[cl][(f4 << 2) + 2] = v.z;
    ts[cl][(f4 << 2) + 3] = v.w;
    __syncthreads();
    int pl = tid >> 3, c4 = tid & 7;
    float4 o;
    o.x = ts[(c4 << 2) + 0][pl];
    o.y = ts[(c4 << 2) + 1][pl];
    o.z = ts[(c4 << 2) + 2][pl];
    o.w = ts[(c4 << 2) + 3][pl];
    float* hp = xT + (size_t)b * NPIX * CCH + (size_t)(px0 + pl) * CCH + ch0 + (c4 << 2);
    *(float4*)hp = o;
}

// ---------------- finalize stats ----------------
__global__ void stats_final_kernel(const float* __restrict__ gamma,
                                   const float* __restrict__ beta)
{
    int bg = blockIdx.x;
    int b = bg >> 5, g = bg & 31;
    int wid = threadIdx.x >> 5, lane = threadIdx.x & 31;
    __shared__ float chs[16], chss[16];
    __shared__ float2 st_sh;

#pragma unroll
    for (int c2 = 0; c2 < 2; c2++) {
        int cl = wid * 2 + c2;
        int ch = g * 16 + cl;
        const float* ps  = g_ps  + ((size_t)(b << 9) + ch) * 128;
        const float* pss = g_pss + ((size_t)(b << 9) + ch) * 128;
        float s = 0.f, ss = 0.f;
#pragma unroll
        for (int i = 0; i < 4; i++) {
            s  += ps[lane + (i << 5)];
            ss += pss[lane + (i << 5)];
        }
#pragma unroll
        for (int o = 16; o > 0; o >>= 1) {
            s  += __shfl_xor_sync(0xffffffffu, s, o);
            ss += __shfl_xor_sync(0xffffffffu, ss, o);
        }
        if (lane == 0) { chs[cl] = s; chss[cl] = ss; }
    }
    __syncthreads();
    if (threadIdx.x == 0) {
        float s = 0.f, ss = 0.f;
#pragma unroll
        for (int i = 0; i < 16; i++) { s += chs[i]; ss += chss[i]; }
        float mean = s * (1.f / (16 * NPIX));
        float var  = ss * (1.f / (16 * NPIX)) - mean * mean;
        st_sh = make_float2(mean, rsqrtf(var + 1e-6f));
    }
    __syncthreads();
    if (threadIdx.x < 16) {
        int cl = threadIdx.x, ch = g * 16 + cl;
        float2 st = st_sh;
        float ga = gamma[ch] * st.y;
        float be = beta[ch] - st.x * ga;
        float sx = chs[cl];
        int idx = (b << 9) + ch;
        g_ga[idx] = ga;
        g_be[idx] = be;
        g_sx[idx] = sx;
        g_hs[idx] = ga * sx + (float)NPIX * be;
    }
}

// ================= gemm256: tf32 NT, CTA 256x128, 256 threads (heavies) =================
#define G256_AF   (64 * A_SUB)
#define G256_BF   (64 * B_SUB)
#define G256_STG  (G256_AF + G256_BF)
#define SMEM256   (2 * G256_STG * 4)

__global__ void __launch_bounds__(256, 1) gemm256(
    const float* __restrict__ A, int lda, long long sA,
    const float* __restrict__ B, int ldb, long long sB,
    float* __restrict__ D, int ldd, long long sD,
    const float* __restrict__ bias, int bias_mode, long long sBias,
    const float* __restrict__ resid,
    const float* __restrict__ cscale,
    float scale, int K, int sym, long long sKsp)
{
    extern __shared__ float smem[];

    int tid = threadIdx.x, wid = tid >> 5, lane = tid & 31;
    int z = blockIdx.z;
    int row0, col0;
    if (sym) {
        int t = blockIdx.x;
        row0 = (t < 2) ? 0 : 256;
        col0 = ((t < 2) ? t : (t - 2)) << 7;
    } else {
        row0 = blockIdx.y << 8;
        col0 = blockIdx.x << 7;
    }

    A += (size_t)z * sA + (size_t)row0 * lda;
    B += (size_t)z * sB + (size_t)col0 * ldb;
    D += (size_t)z * sD;
    if (sym) {
        A += (size_t)blockIdx.y * K;
        B += (size_t)blockIdx.y * K;
        D += (size_t)blockIdx.y * sKsp;
    }
    if (resid) resid += (size_t)z * sD;

    const int r_  = tid >> 3;
    const int c0_ = (tid & 7) << 2;
    const int kt_ = c0_ >> 3;
    int offA2[8], offB[4];
#pragma unroll
    for (int i = 0; i < 8; i++) {
        int r = r_ + (i << 5);
        int mt = r >> 4, rr = r & 15;
        int regA = (((c0_ & 7) >= 4) ? 2 : 0) + ((rr >> 3) & 1);
        offA2[i] = (mt * 4 + kt_) * A_SUB + ((rr & 7) << 4) + regA;
    }
#pragma unroll
    for (int i = 0; i < 4; i++) {
        int r = r_ + (i << 5);
        int nt = r >> 3, nn = r & 7;
        int regB = ((c0_ & 7) >= 4) ? 1 : 0;
        offB[i] = G256_AF + (nt * 4 + kt_) * B_SUB + (nn << 3) + regB;
    }

    const float* aG = A + (size_t)r_ * lda + c0_;
    const float* bG = B + (size_t)r_ * ldb + c0_;
    const size_t aStep = (size_t)32 * lda;
    const size_t bStep = (size_t)32 * ldb;

    const int wm4 = (wid & 3) * 4;
    const int wn8 = (wid >> 2) * 8;

    float acc[4][8][4];
#pragma unroll
    for (int mt = 0; mt < 4; mt++)
#pragma unroll
        for (int nt = 0; nt < 8; nt++)
#pragma unroll
            for (int g = 0; g < 4; g++) acc[mt][nt][g] = 0.f;

    const int NK = K >> 5;
    float4 ra[8], rb[4];

    auto stage_load = [&](int s) {
        const float* aN = aG + (size_t)s * 32;
        const float* bN = bG + (size_t)s * 32;
#pragma unroll
        for (int i = 0; i < 8; i++) ra[i] = *(const float4*)(aN + i * aStep);
#pragma unroll
        for (int i = 0; i < 4; i++) rb[i] = *(const float4*)(bN + i * bStep);
    };
    auto stage_store = [&](float* base) {
#pragma unroll
        for (int i = 0; i < 8; i++) {
            float* sa = base + offA2[i];
            sa[0]  = tf32r(ra[i].x);
            sa[4]  = tf32r(ra[i].y);
            sa[8]  = tf32r(ra[i].z);
            sa[12] = tf32r(ra[i].w);
        }
#pragma unroll
        for (int i = 0; i < 4; i++) {
            float* sb = base + offB[i];
            sb[0] = tf32r(rb[i].x);
            sb[2] = tf32r(rb[i].y);
            sb[4] = tf32r(rb[i].z);
            sb[6] = tf32r(rb[i].w);
        }
    };

    stage_load(0);
    stage_store(smem);
    __syncthreads();

    for (int s = 0; s < NK; s++) {
        if (s + 1 < NK) stage_load(s + 1);
        const float* cS = smem + (s & 1) * G256_STG;
#pragma unroll
        for (int kt = 0; kt < 4; kt++) {
            uint4 af[4]; uint2 bf[8];
#pragma unroll
            for (int mt = 0; mt < 4; mt++)
                af[mt] = *(const uint4*)(cS + ((wm4 + mt) * 4 + kt) * A_SUB + (lane << 2));
#pragma unroll
            for (int nt = 0; nt < 8; nt++)
                bf[nt] = *(const uint2*)(cS + G256_AF + ((wn8 + nt) * 4 + kt) * B_SUB + (lane << 1));
#pragma unroll
            for (int mt = 0; mt < 4; mt++)
#pragma unroll
                for (int nt = 0; nt < 8; nt++)
                    mma_tf32(acc[mt][nt], &af[mt].x, &bf[nt].x);
        }
        if (s + 1 < NK) {
            stage_store(smem + ((s + 1) & 1) * G256_STG);
            __syncthreads();
        }
    }

    const int lane4 = lane >> 2, laneq = lane & 3;
    const int wrow = row0 + (wid & 3) * 64;
    const int wcol = col0 + (wid >> 2) * 64;
#pragma unroll
    for (int mt = 0; mt < 4; mt++) {
#pragma unroll
        for (int half = 0; half < 2; half++) {
            int r = wrow + mt * 16 + lane4 + half * 8;
            float rb_ = (bias_mode == 1) ? bias[(size_t)z * sBias + r] : 0.f;
            float* drow = D + (size_t)r * ldd + wcol;
            const float* rrow = resid ? (resid + (size_t)r * ldd + wcol) : nullptr;
#pragma unroll
            for (int nt = 0; nt < 8; nt++) {
                int c = nt * 8 + laneq * 2;
                float2 o;
                o.x = acc[mt][nt][half * 2 + 0] * scale;
                o.y = acc[mt][nt][half * 2 + 1] * scale;
                if (cscale) {
                    o.x *= cscale[(size_t)z * CCH + wcol + c];
                    o.y *= cscale[(size_t)z * CCH + wcol + c + 1];
                }
                o.x += rb_; o.y += rb_;
                if (rrow) { o.x += rrow[c]; o.y += rrow[c + 1]; }
                *(float2*)(drow + c) = o;
            }
        }
    }
}

// ================= gemm128: CTA 128x128, 128 threads, 2 CTAs/SM (smalls) =================
#define G128_STA  4224
#define G128_STG  8448
#define SMEM128   (2 * G128_STG * 4)
#define G128_APL  2112
#define G128_BPL  2112
#define G128_BHI  G128_STA
#define G128_BLO  (G128_STA + G128_BPL)

template<int PREC>
__global__ void __launch_bounds__(128, 2) gemm128(
    const float* __restrict__ A, int lda, long long sA,
    const float* __restrict__ B, int ldb, long long sB,
    float* __restrict__ D, int ldd, long long sD,
    const float* __restrict__ cscale,
    float scale, int K)
{
    extern __shared__ uint32_t smem_u[];

    int tid = threadIdx.x, wid = tid >> 5, lane = tid & 31;
    int z = blockIdx.z;
    int row0 = blockIdx.y << 7, col0 = blockIdx.x << 7;

    A += (size_t)z * sA + (size_t)row0 * lda;
    B += (size_t)z * sB + (size_t)col0 * ldb;
    D += (size_t)z * sD;

    const int r_  = tid >> 3;
    const int c0_ = (tid & 7) << 2;
    const int kt4_  = c0_ >> 3;
    const int kt16_ = c0_ >> 4;
    const int kp_   = (c0_ & 15) >> 1;
    const int khi_  = kp_ >> 2, kpm_ = kp_ & 3;

    int offA[8], offB[8];
#pragma unroll
    for (int i = 0; i < 8; i++) {
        int row = r_ + (i << 4);
        int mt = row >> 4, rr = row & 15;
        if (PREC == 0) {
            int regA = (((c0_ & 7) >= 4) ? 2 : 0) + (rr >> 3);
            offA[i] = (mt * 4 + kt4_) * A_SUB + ((rr & 7) << 4) + regA;
        } else {
            int gr = rr & 7, hf = rr >> 3;
            offA[i] = (mt * 2 + kt16_) * A_SUB + (gr * 4 + kpm_) * 4 + hf + (khi_ << 1);
        }
    }
#pragma unroll
    for (int i = 0; i < 8; i++) {
        int n = r_ + (i << 4);
        int nt = n >> 3, nn = n & 7;
        if (PREC == 0) {
            int regB = ((c0_ & 7) >= 4) ? 1 : 0;
            offB[i] = G128_STA + (nt * 4 + kt4_) * B_SUB + (nn << 3) + regB;
        } else {
            offB[i] = G128_BHI + (nt * 2 + kt16_) * B_SUB + (nn * 4 + kpm_) * 2 + khi_;
        }
    }

    const float* aG = A + (size_t)r_ * lda + c0_;
    const float* bG = B + (size_t)r_ * ldb + c0_;
    const size_t aStep = (size_t)16 * lda;
    const size_t bStep = (size_t)16 * ldb;

    const int wm4 = (wid & 1) * 4;
    const int wn8 = (wid >> 1) * 8;

    float acc[4][8][4];
#pragma unroll
    for (int mt = 0; mt < 4; mt++)
#pragma unroll
        for (int nt = 0; nt < 8; nt++)
#pragma unroll
            for (int g = 0; g < 4; g++) acc[mt][nt][g] = 0.f;

    const int NK = K >> 5;
    float4 ra[8], rb[8];

    auto stage_load = [&](int s) {
        const float* aN = aG + (size_t)s * 32;
        const float* bN = bG + (size_t)s * 32;
#pragma unroll
        for (int i = 0; i < 8; i++) ra[i] = *(const float4*)(aN + i * aStep);
#pragma unroll
        for (int i = 0; i < 8; i++) rb[i] = *(const float4*)(bN + i * bStep);
    };

    auto stage_store = [&](uint32_t* sb) {
        if (PREC == 0) {
            float* sf = (float*)sb;
#pragma unroll
            for (int i = 0; i < 8; i++) {
                float* sa = sf + offA[i];
                sa[0]  = tf32r(ra[i].x);
                sa[4]  = tf32r(ra[i].y);
                sa[8]  = tf32r(ra[i].z);
                sa[12] = tf32r(ra[i].w);
            }
#pragma unroll
            for (int i = 0; i < 8; i++) {
                float* sp = sf + offB[i];
                sp[0] = tf32r(rb[i].x);
                sp[2] = tf32r(rb[i].y);
                sp[4] = tf32r(rb[i].z);
                sp[6] = tf32r(rb[i].w);
            }
        } else {
#pragma unroll
            for (int i = 0; i < 8; i++) {
                uint32_t h01, l01, h23, l23;
                bsplit2(ra[i].x, ra[i].y, h01, l01);
                bsplit2(ra[i].z, ra[i].w, h23, l23);
                sb[offA[i]]                  = h01;
                sb[offA[i] + 4]              = h23;
                sb[G128_APL + offA[i]]       = l01;
                sb[G128_APL + offA[i] + 4]   = l23;
            }
#pragma unroll
            for (int i = 0; i < 8; i++) {
                uint32_t h01, l01, h23, l23;
                bsplit2(rb[i].x, rb[i].y, h01, l01);
                bsplit2(rb[i].z, rb[i].w, h23, l23);
                sb[offB[i]]                  = h01;
                sb[offB[i] + 2]              = h23;
                sb[G128_BPL + offB[i]]       = l01;
                sb[G128_BPL + offB[i] + 2]   = l23;
            }
        }
    };

    stage_load(0);
    stage_store(smem_u);
    __syncthreads();

    for (int s = 0; s < NK; s++) {
        if (s + 1 < NK) stage_load(s + 1);
        const uint32_t* cS = smem_u + (s & 1) * G128_STG;
        if (PREC == 0) {
#pragma unroll
            for (int kt = 0; kt < 4; kt++) {
                uint4 af[4]; uint2 bf[8];
#pragma unroll
                for (int mt = 0; mt < 4; mt++)
                    af[mt] = *(const uint4*)(cS + ((wm4 + mt) * 4 + kt) * A_SUB + (lane << 2));
#pragma unroll
                for (int nt = 0; nt < 8; nt++)
                    bf[nt] = *(const uint2*)(cS + G128_STA + ((wn8 + nt) * 4 + kt) * B_SUB + (lane << 1));
#pragma unroll
                for (int mt = 0; mt < 4; mt++)
#pragma unroll
                    for (int nt = 0; nt < 8; nt++)
                        mma_tf32(acc[mt][nt], &af[mt].x, &bf[nt].x);
            }
        } else {
#pragma unroll
            for (int kt = 0; kt < 2; kt++) {
                uint4 af[4]; uint2 bf[8];
#pragma unroll
                for (int mt = 0; mt < 4; mt++)
                    af[mt] = *(const uint4*)(cS + ((wm4 + mt) * 2 + kt) * A_SUB + (lane << 2));
#pragma unroll
                for (int nt = 0; nt < 8; nt++)
                    bf[nt] = *(const uint2*)(cS + G128_BHI + ((wn8 + nt) * 2 + kt) * B_SUB + (lane << 1));
#pragma unroll
                for (int mt = 0; mt < 4; mt++)
#pragma unroll
                    for (int nt = 0; nt < 8; nt++)
                        mma_bf16(acc[mt][nt], &af[mt].x, &bf[nt].x);
                {
                    uint4 al[4];
#pragma unroll
                    for (int mt = 0; mt < 4; mt++)
                        al[mt] = *(const uint4*)(cS + G128_APL + ((wm4 + mt) * 2 + kt) * A_SUB + (lane << 2));
#pragma unroll
                    for (int mt = 0; mt < 4; mt++)
#pragma unroll
                        for (int nt = 0; nt < 8; nt++)
                            mma_bf16(acc[mt][nt], &al[mt].x, &bf[nt].x);
                }
                {
                    uint2 bl[8];
#pragma unroll
                    for (int nt = 0; nt < 8; nt++)
                        bl[nt] = *(const uint2*)(cS + G128_BLO + ((wn8 + nt) * 2 + kt) * B_SUB + (lane << 1));
#pragma unroll
                    for (int mt = 0; mt < 4; mt++)
#pragma unroll
                        for (int nt = 0; nt < 8; nt++)
                            mma_bf16(acc[mt][nt], &af[mt].x, &bl[nt].x);
                }
            }
        }
        if (s + 1 < NK) {
            stage_store(smem_u + ((s + 1) & 1) * G128_STG);
            __syncthreads();
        }
    }

    const int lane4 = lane >> 2, laneq = lane & 3;
    const int wrow = row0 + (wid & 1) * 64;
    const int wcol = col0 + (wid >> 1) * 64;
#pragma unroll
    for (int mt = 0; mt < 4; mt++) {
#pragma unroll
        for (int half = 0; half < 2; half++) {
            int r = wrow + mt * 16 + lane4 + half * 8;
            float* drow = D + (size_t)r * ldd + wcol;
#pragma unroll
            for (int nt = 0; nt < 8; nt++) {
                int c = nt * 8 + laneq * 2;
                float2 o;
                o.x = acc[mt][nt][half * 2 + 0] * scale;
                o.y = acc[mt][nt][half * 2 + 1] * scale;
                if (cscale) {
                    o.x *= cscale[(size_t)z * CCH + wcol + c];
                    o.y *= cscale[(size_t)z * CCH + wcol + c + 1];
                }
                *(float2*)(drow + c) = o;
            }
        }
    }
}

// ---------------- reduce split-K Gram partials + GN rank-1 corrections ----------------
__global__ void __launch_bounds__(256) reduce_g_kernel(const float* __restrict__ Gp,
                                                       float* __restrict__ G)
{
    const size_t per = (size_t)BATCH * CCH * CCH;
    int b = blockIdx.y;
    int idx = (blockIdx.x * 256 + threadIdx.x) << 2;
    int i = idx >> 9, j = idx & 511;
    if (i < 256 && j >= 256) return;
    size_t off = (size_t)b * CCH * CCH + idx;
    float4 s0 = *(const float4*)(Gp + off);
    float4 s1 = *(const float4*)(Gp + per + off);
    float4 s2 = *(const float4*)(Gp + 2 * per + off);
    float4 s3 = *(const float4*)(Gp + 3 * per + off);
    int ri = (b << 9) + i, rj = (b << 9) + j;
    float gai = g_ga[ri], hsxi = gai * g_sx[ri], bei = g_be[ri];
    float4 gaj = *(const float4*)(g_ga + rj);
    float4 bej = *(const float4*)(g_be + rj);
    float4 hsj = *(const float4*)(g_hs + rj);
    float4 o;
    o.x = gai * gaj.x * ((s0.x + s1.x) + (s2.x + s3.x)) + hsxi * bej.x + bei * hsj.x;
    o.y = gai * gaj.y * ((s0.y + s1.y) + (s2.y + s3.y)) + hsxi * bej.y + bei * hsj.y;
    o.z = gai * gaj.z * ((s0.z + s1.z) + (s2.z + s3.z)) + hsxi * bej.z + bei * hsj.z;
    o.w = gai * gaj.w * ((s0.w + s1.w) + (s2.w + s3.w)) + hsxi * bej.w + bei * hsj.w;
    *(float4*)(G + off) = o;
}

// ---------------- mirror upper-right block of symmetric G ----------------
__global__ void __launch_bounds__(256) mirror_kernel(float* __restrict__ G)
{
    __shared__ float t[32][33];
    float* Gb = G + (size_t)blockIdx.z * CCH * CCH;
    int i0 = blockIdx.y << 5, j0 = 256 + (blockIdx.x << 5);
    int lx = threadIdx.x & 31, ly = threadIdx.x >> 5;
#pragma unroll
    for (int ii = 0; ii < 4; ii++)
        t[ly + ii * 8][lx] = Gb[(size_t)(j0 + ly + ii * 8) * CCH + i0 + lx];
    __syncthreads();
#pragma unroll
    for (int ii = 0; ii < 4; ii++)
        Gb[(size_t)(i0 + ly + ii * 8) * CCH + j0 + lx] = t[lx][ly + ii * 8];
}

// ---------------- softmax with rank-1 bias corrections + fused t ----------------
__global__ void softmax_kernel(const float* __restrict__ S, float* __restrict__ attn,
                               const float* __restrict__ u, const float* __restrict__ w,
                               const float* __restrict__ bq, const float* __restrict__ bk,
                               const float* __restrict__ v1, const float* __restrict__ bv,
                               float* __restrict__ tvec, float scale)
{
    int gw = (blockIdx.x * blockDim.x + threadIdx.x) >> 5;
    int lane = threadIdx.x & 31;
    if (gw >= BATCH * CCH) return;
    int b = gw >> 9, c = gw & 511;
    const float* row = S + (size_t)gw * CCH;
    float* orow = attn + (size_t)gw * CCH;
    float uc = u[(b << 9) + c], bqc = bq[c];
    float v[16];
    float m = -3.4e38f;
#pragma unroll
    for (int i = 0; i < 16; i++) {
        int d = lane + (i << 5);
        float bkd = bk[d], wd = w[(b << 9) + d];
        v[i] = scale * (row[d] + uc * bkd + bqc * wd + (float)NPIX * bqc * bkd);
        m = fmaxf(m, v[i]);
    }
#pragma unroll
    for (int o = 16; o > 0; o >>= 1) m = fmaxf(m, __shfl_xor_sync(0xffffffffu, m, o));
    float s = 0.f;
#pragma unroll
    for (int i = 0; i < 16; i++) { v[i] = __expf(v[i] - m); s += v[i]; }
#pragma unroll
    for (int o = 16; o > 0; o >>= 1) s += __shfl_xor_sync(0xffffffffu, s, o);
    float inv = 1.f / s;
    float tdot = 0.f;
#pragma unroll
    for (int i = 0; i < 16; i++) {
        int d = lane + (i << 5);
        float av = v[i] * inv;
        orow[d] = av;
        tdot += av * (v1[(b << 9) + d] + bv[d]);
    }
#pragma unroll
    for (int o = 16; o > 0; o >>= 1) tdot += __shfl_xor_sync(0xffffffffu, tdot, o);
    if (lane == 0) tvec[gw] = tdot;
}

// ---------------- 512x512 transpose (per batch z) ----------------
__global__ void __launch_bounds__(256) transpose_kernel(
    const float* __restrict__ in, float* __restrict__ out, long long sIn, long long sOut)
{
    __shared__ float t[32][33];
    int z = blockIdx.z;
    in  += (size_t)z * sIn;
    out += (size_t)z * sOut;
    int x0 = blockIdx.x << 5, y0 = blockIdx.y << 5;
    int lx = threadIdx.x & 31, ly = threadIdx.x >> 5;
#pragma unroll
    for (int i = 0; i < 4; i++)
        t[ly + i * 8][lx] = in[(size_t)(y0 + ly + i * 8) * CCH + x0 + lx];
    __syncthreads();
#pragma unroll
    for (int i = 0; i < 4; i++)
        out[(size_t)(x0 + ly + i * 8) * CCH + y0 + lx] = t[lx][ly + i * 8];
}

// ---------------- combined u/w/v1 matvecs ----------------
__global__ void matvec_uwv_kernel(const float* __restrict__ Wq, const float* __restrict__ Wk,
                                  const float* __restrict__ Wv,
                                  const float* __restrict__ hs, const float* __restrict__ be,
                                  float* __restrict__ u, float* __restrict__ w,
                                  float* __restrict__ v1)
{
    int zz = blockIdx.z;
    const float* W = (zz == 0) ? Wq : (zz == 1) ? Wk : Wv;
    const float* vec = (zz == 2) ? be : hs;
    float* y = (zz == 0) ? u : (zz == 1) ? w : v1;
    int b = blockIdx.y;
    int m = (blockIdx.x << 3) + (threadIdx.x >> 5);
    int lane = threadIdx.x & 31;
    const float* wr = W + (size_t)m * CCH;
    const float* vv = vec + (size_t)b * CCH;
    float s = 0.f;
    for (int k = lane; k < CCH; k += 32) s += wr[k] * vv[k];
#pragma unroll
    for (int o = 16; o > 0; o >>= 1) s += __shfl_xor_sync(0xffffffffu, s, o);
    if (lane == 0) y[(size_t)b * CCH + m] = s;
}

// ---------------- r = Wo.t + bo ----------------
__global__ void matvec_r_kernel(const float* __restrict__ Wo, const float* __restrict__ tvec,
                                const float* __restrict__ bo, float* __restrict__ r)
{
    int b = blockIdx.y;
    int m = (blockIdx.x << 3) + (threadIdx.x >> 5);
    int lane = threadIdx.x & 31;
    const float* wr = Wo + (size_t)m * CCH;
    const float* vv = tvec + (size_t)b * CCH;
    float s = 0.f;
    for (int k = lane; k < CCH; k += 32) s += wr[k] * vv[k];
#pragma unroll
    for (int o = 16; o > 0; o >>= 1) s += __shfl_xor_sync(0xffffffffu, s, o);
    if (lane == 0) r[(size_t)b * CCH + m] = s + bo[m];
}

// ---------------- launch ----------------
extern "C" void kernel_launch(void* const* d_in, const int* in_sizes, int n_in,
                              void* d_out, int out_size)
{
    const float* x     = (const float*)d_in[0];
    const float* gamma = (const float*)d_in[1];
    const float* beta  = (const float*)d_in[2];
    const float* Wq    = (const float*)d_in[3];
    const float* bq    = (const float*)d_in[4];
    const float* Wk    = (const float*)d_in[5];
    const float* bk    = (const float*)d_in[6];
    const float* Wv    = (const float*)d_in[7];
    const float* bv    = (const float*)d_in[8];
    const float* Wo    = (const float*)d_in[9];
    const float* bo    = (const float*)d_in[10];
    float* out = (float*)d_out;

    float *xT, *Gp, *G, *T1, *S, *attn, *attnT, *T2, *P, *WvT;
    float *ga, *be, *hs, *u, *w, *v1, *t, *r;
    cudaGetSymbolAddress((void**)&xT,    g_xT);
    cudaGetSymbolAddress((void**)&Gp,    g_Gp);
    cudaGetSymbolAddress((void**)&G,     g_G);
    cudaGetSymbolAddress((void**)&T1,    g_T1);
    cudaGetSymbolAddress((void**)&S,     g_S);
    cudaGetSymbolAddress((void**)&attn,  g_attn);
    cudaGetSymbolAddress((void**)&attnT, g_attnT);
    cudaGetSymbolAddress((void**)&T2,    g_T2);
    cudaGetSymbolAddress((void**)&P,     g_P);
    cudaGetSymbolAddress((void**)&WvT,   g_WvT);
    cudaGetSymbolAddress((void**)&ga,    g_ga);
    cudaGetSymbolAddress((void**)&be,    g_be);
    cudaGetSymbolAddress((void**)&hs,    g_hs);
    cudaGetSymbolAddress((void**)&u,     g_u);
    cudaGetSymbolAddress((void**)&w,     g_w);
    cudaGetSymbolAddress((void**)&v1,    g_v1);
    cudaGetSymbolAddress((void**)&t,     g_t);
    cudaGetSymbolAddress((void**)&r,     g_r);

    cudaFuncSetAttribute((const void*)gemm256,     cudaFuncAttributeMaxDynamicSharedMemorySize, SMEM256);
    cudaFuncSetAttribute((const void*)gemm128<0>,  cudaFuncAttributeMaxDynamicSharedMemorySize, SMEM128);
    cudaFuncSetAttribute((const void*)gemm128<1>,  cudaFuncAttributeMaxDynamicSharedMemorySize, SMEM128);

    const long long sF  = (long long)CCH * NPIX;
    const long long sAt = (long long)CCH * CCH;
    const long long sKsp = (long long)BATCH * CCH * CCH;
    const float scale = 1.0f / sqrtf((float)CCH);

    // side stream + events for graph-level parallelism (host-side setup; capture-safe)
    cudaStream_t s2;
    cudaStreamCreateWithFlags(&s2, cudaStreamNonBlocking);
    cudaEvent_t eFork, eGram, eSmax, eR;
    cudaEventCreateWithFlags(&eFork, cudaEventDisableTiming);
    cudaEventCreateWithFlags(&eGram, cudaEventDisableTiming);
    cudaEventCreateWithFlags(&eSmax, cudaEventDisableTiming);
    cudaEventCreateWithFlags(&eR,    cudaEventDisableTiming);

    // ---- fork: Gram on s2 (needs only x) || prologue chain on stream 0 ----
    cudaEventRecord(eFork, 0);
    cudaStreamWaitEvent(s2, eFork, 0);

    gemm256<<<dim3(6, KSPLIT, BATCH), 256, SMEM256, s2>>>(
        x, NPIX, sF, x, NPIX, sF, Gp, CCH, sAt,
        nullptr, 0, 0, nullptr, nullptr, 1.f, NPIX / KSPLIT, 1, sKsp);
    cudaEventRecord(eGram, s2);

    tr_stats_kernel<<<dim3(NPIX / 32, CCH / 32, BATCH), 256>>>(x, xT);
    stats_final_kernel<<<BATCH * 32, 256>>>(gamma, beta);
    matvec_uwv_kernel<<<dim3(CCH / 8, BATCH, 3), 256>>>(Wq, Wk, Wv, hs, be, u, w, v1);
    transpose_kernel<<<dim3(16, 16, 1), 256>>>(Wv, WvT, 0, 0);

    // ---- join: reduce_g needs Gram partials + stats ----
    cudaStreamWaitEvent(0, eGram, 0);
    reduce_g_kernel<<<dim3(256, BATCH), 256>>>(Gp, G);
    mirror_kernel<<<dim3(8, 8, BATCH), 256>>>(G);

    // T1 = Wq G; S = T1 Wk^T   (split-bf16 smalls)
    gemm128<1><<<dim3(4, 4, BATCH), 128, SMEM128>>>(
        Wq, CCH, 0, G, CCH, sAt, T1, CCH, sAt, nullptr, 1.f, CCH);
    gemm128<1><<<dim3(4, 4, BATCH), 128, SMEM128>>>(
        T1, CCH, sAt, Wk, CCH, 0, S, CCH, sAt, nullptr, 1.f, CCH);

    // softmax (fused t)
    softmax_kernel<<<(BATCH * CCH * 32) / 256, 256>>>(S, attn, u, w, bq, bk, v1, bv, t, scale);

    // ---- fork: matvec_r on s2 (needs t) || transpose/T2/P on stream 0 ----
    cudaEventRecord(eSmax, 0);
    cudaStreamWaitEvent(s2, eSmax, 0);
    matvec_r_kernel<<<dim3(CCH / 8, BATCH), 256, 0, s2>>>(Wo, t, bo, r);
    cudaEventRecord(eR, s2);

    transpose_kernel<<<dim3(16, 16, BATCH), 256>>>(attn, attnT, sAt, sAt);
    gemm128<0><<<dim3(4, 4, BATCH), 128, SMEM128>>>(
        Wo, CCH, 0, attnT, CCH, sAt, T2, CCH, sAt, nullptr, 1.f, CCH);
    gemm128<0><<<dim3(4, 4, BATCH), 128, SMEM128>>>(
        T2, CCH, sAt, WvT, CCH, 0, P, CCH, sAt, ga, 1.f, CCH);

    // ---- join: out GEMM needs P, r, xT ----
    cudaStreamWaitEvent(0, eR, 0);
    gemm256<<<dim3(NPIX / 128, 2, BATCH), 256, SMEM256>>>(
        P, CCH, sAt, xT, CCH, sF, out, NPIX, sF, r, 1, CCH, x, nullptr, 1.f, CCH, 0, 0);

    cudaEventDestroy(eFork);
    cudaEventDestroy(eGram);
    cudaEventDestroy(eSmax);
    cudaEventDestroy(eR);
    cudaStreamDestroy(s2);
}